// round 4
// baseline (speedup 1.0000x reference)
#include <cuda_runtime.h>
#include <cuda_bf16.h>
#include <cstdint>

// Problem constants
#define NN      8192
#define DD      512
#define SS      64
#define BI      128
#define BJ      128
#define DKC     16          // k-chunk
#define NSPLIT  8           // i-range splits (1024 rows each)
#define PADR    132         // smem row pad (floats): 528B, 16B-aligned, conflict-light

#define INV2SIG 0.0009765625f   // 1/(2*512)

// Scratch (device globals; no runtime allocation)
__device__ float  g_sq[NN];
__device__ float  g_Epart[NSPLIT * SS * NN];      // 16 MB partial E
__device__ double g_partial[2048];                // per-block loss partials

// ---------------------------------------------------------------------------
// Kernel 1: row squared norms. One warp per row.
// ---------------------------------------------------------------------------
__global__ void rownorm_kernel(const float* __restrict__ X) {
    int row  = blockIdx.x * 8 + (threadIdx.x >> 5);
    int lane = threadIdx.x & 31;
    const float4* xr = reinterpret_cast<const float4*>(X + (size_t)row * DD);
    float s = 0.f;
#pragma unroll
    for (int q = 0; q < 4; q++) {
        float4 v = xr[lane + q * 32];
        s += v.x * v.x + v.y * v.y + v.z * v.z + v.w * v.w;
    }
#pragma unroll
    for (int o = 16; o; o >>= 1) s += __shfl_xor_sync(0xFFFFFFFFu, s, o);
    if (lane == 0) g_sq[row] = s;
}

// ---------------------------------------------------------------------------
// Kernel 2: fused  K-tile GEMM + exp + E accumulation.
// grid = (64 J-tiles, 8 I-splits), 256 threads.
// Each block: for 8 i-tiles of 128 rows, compute K[128x128] = exp RBF of
// X[i-tile] x X[j-tile]^T, then E[s, jtile] += W[i-tile]^T K  (E in regs).
// ---------------------------------------------------------------------------
__global__ __launch_bounds__(256, 1)
void kpca_main_kernel(const float* __restrict__ X, const float* __restrict__ W) {
    __shared__ float As[DKC][PADR];
    __shared__ float Bs[DKC][PADR];
    __shared__ float Ksm[32][PADR];
    __shared__ float Wsm[32][SS];

    const int jt     = blockIdx.x;
    const int isplit = blockIdx.y;
    const int j0     = jt * BJ;
    const int t  = threadIdx.x;
    const int tx = t & 15;
    const int ty = t >> 4;

    // E accumulators: s = ty*4+v  (64 = 16*4),  j = j0 + tx*8+u (128 = 16*8)
    float Ereg[4][8];
#pragma unroll
    for (int v = 0; v < 4; v++)
#pragma unroll
        for (int u = 0; u < 8; u++) Ereg[v][u] = 0.f;

    float sqj[8];
#pragma unroll
    for (int u = 0; u < 8; u++) sqj[u] = g_sq[j0 + tx * 8 + u];

    // global-load mapping for A/B tiles: 128 rows x 16 cols, 2 float4 / thread
    const int lr  = t >> 2;            // 0..63
    const int lc4 = (t & 3) * 4;       // {0,4,8,12}

    for (int it = 0; it < 8; it++) {
        const int i0 = isplit * 1024 + it * BI;

        float acc[8][8];
#pragma unroll
        for (int u = 0; u < 8; u++)
#pragma unroll
            for (int v = 0; v < 8; v++) acc[u][v] = 0.f;

        for (int kc = 0; kc < DD; kc += DKC) {
            // prefetch to registers
            float4 av0 = *reinterpret_cast<const float4*>(&X[(size_t)(i0 + lr)      * DD + kc + lc4]);
            float4 av1 = *reinterpret_cast<const float4*>(&X[(size_t)(i0 + lr + 64) * DD + kc + lc4]);
            float4 bv0 = *reinterpret_cast<const float4*>(&X[(size_t)(j0 + lr)      * DD + kc + lc4]);
            float4 bv1 = *reinterpret_cast<const float4*>(&X[(size_t)(j0 + lr + 64) * DD + kc + lc4]);

            __syncthreads();   // previous k-chunk fully consumed
            As[lc4 + 0][lr] = av0.x;  As[lc4 + 1][lr] = av0.y;
            As[lc4 + 2][lr] = av0.z;  As[lc4 + 3][lr] = av0.w;
            As[lc4 + 0][lr + 64] = av1.x;  As[lc4 + 1][lr + 64] = av1.y;
            As[lc4 + 2][lr + 64] = av1.z;  As[lc4 + 3][lr + 64] = av1.w;
            Bs[lc4 + 0][lr] = bv0.x;  Bs[lc4 + 1][lr] = bv0.y;
            Bs[lc4 + 2][lr] = bv0.z;  Bs[lc4 + 3][lr] = bv0.w;
            Bs[lc4 + 0][lr + 64] = bv1.x;  Bs[lc4 + 1][lr + 64] = bv1.y;
            Bs[lc4 + 2][lr + 64] = bv1.z;  Bs[lc4 + 3][lr + 64] = bv1.w;
            __syncthreads();

#pragma unroll
            for (int k = 0; k < DKC; k++) {
                float4 a0 = *reinterpret_cast<const float4*>(&As[k][ty * 8]);
                float4 a1 = *reinterpret_cast<const float4*>(&As[k][ty * 8 + 4]);
                float4 b0 = *reinterpret_cast<const float4*>(&Bs[k][tx * 8]);
                float4 b1 = *reinterpret_cast<const float4*>(&Bs[k][tx * 8 + 4]);
                float a[8] = {a0.x, a0.y, a0.z, a0.w, a1.x, a1.y, a1.z, a1.w};
                float b[8] = {b0.x, b0.y, b0.z, b0.w, b1.x, b1.y, b1.z, b1.w};
#pragma unroll
                for (int u = 0; u < 8; u++)
#pragma unroll
                    for (int v = 0; v < 8; v++)
                        acc[u][v] = fmaf(a[u], b[v], acc[u][v]);
            }
        }

        // epilogue: d2 -> exp
        float sqi[8];
#pragma unroll
        for (int u = 0; u < 8; u++) sqi[u] = g_sq[i0 + ty * 8 + u];
#pragma unroll
        for (int u = 0; u < 8; u++)
#pragma unroll
            for (int v = 0; v < 8; v++)
                acc[u][v] = __expf((2.f * acc[u][v] - sqi[u] - sqj[v]) * INV2SIG);

        // E accumulation: 4 chunks of 32 K-rows
        const int wr  = t >> 3;          // 0..31
        const int wc  = (t & 7) * 8;     // 0..56
        for (int c = 0; c < 4; c++) {
            __syncthreads();    // previous chunk's Ksm/Wsm reads done
            if ((ty >> 2) == c) {
                const int tyl = ty & 3;
#pragma unroll
                for (int u = 0; u < 8; u++) {
                    *reinterpret_cast<float4*>(&Ksm[tyl * 8 + u][tx * 8]) =
                        make_float4(acc[u][0], acc[u][1], acc[u][2], acc[u][3]);
                    *reinterpret_cast<float4*>(&Ksm[tyl * 8 + u][tx * 8 + 4]) =
                        make_float4(acc[u][4], acc[u][5], acc[u][6], acc[u][7]);
                }
            }
            {
                const float* wp = &W[(size_t)(i0 + c * 32 + wr) * SS + wc];
                *reinterpret_cast<float4*>(&Wsm[wr][wc])     = *reinterpret_cast<const float4*>(wp);
                *reinterpret_cast<float4*>(&Wsm[wr][wc + 4]) = *reinterpret_cast<const float4*>(wp + 4);
            }
            __syncthreads();

#pragma unroll
            for (int ii = 0; ii < 32; ii++) {
                float4 w4 = *reinterpret_cast<const float4*>(&Wsm[ii][ty * 4]);
                float4 k0 = *reinterpret_cast<const float4*>(&Ksm[ii][tx * 8]);
                float4 k1 = *reinterpret_cast<const float4*>(&Ksm[ii][tx * 8 + 4]);
                float w[4] = {w4.x, w4.y, w4.z, w4.w};
                float kk[8] = {k0.x, k0.y, k0.z, k0.w, k1.x, k1.y, k1.z, k1.w};
#pragma unroll
                for (int v = 0; v < 4; v++)
#pragma unroll
                    for (int u = 0; u < 8; u++)
                        Ereg[v][u] = fmaf(w[v], kk[u], Ereg[v][u]);
            }
        }
    }

    // write partial E
#pragma unroll
    for (int v = 0; v < 4; v++) {
        float* dst = &g_Epart[(size_t)isplit * (SS * NN) + (size_t)(ty * 4 + v) * NN + j0 + tx * 8];
        *reinterpret_cast<float4*>(dst)     = make_float4(Ereg[v][0], Ereg[v][1], Ereg[v][2], Ereg[v][3]);
        *reinterpret_cast<float4*>(dst + 4) = make_float4(Ereg[v][4], Ereg[v][5], Ereg[v][6], Ereg[v][7]);
    }
}

// ---------------------------------------------------------------------------
// Kernel 3: combine E partials, per-element loss contribution, block reduce.
// grid 2048 x 256; one element per thread. Deterministic tree reduction.
// ---------------------------------------------------------------------------
__global__ void finalize_kernel(const float* __restrict__ W,
                                const float* __restrict__ invl) {
    const int tid = threadIdx.x;
    const int idx = blockIdx.x * 256 + tid;   // 0..524287
    const int s = idx >> 13;                  // /8192
    const int j = idx & (NN - 1);

    float E = 0.f;
#pragma unroll
    for (int p = 0; p < NSPLIT; p++) E += g_Epart[(size_t)p * (SS * NN) + idx];

    double Ed = (double)E;
    double contrib = 0.5 * Ed * ((double)W[(size_t)j * SS + s] - (double)invl[s] * Ed);

    __shared__ double sm[256];
    sm[tid] = contrib;
    __syncthreads();
#pragma unroll
    for (int o = 128; o; o >>= 1) {
        if (tid < o) sm[tid] += sm[tid + o];
        __syncthreads();
    }
    if (tid == 0) g_partial[blockIdx.x] = sm[0];
}

// ---------------------------------------------------------------------------
// Kernel 4: final deterministic reduction + nonlinearity.
// ---------------------------------------------------------------------------
__global__ void final_reduce_kernel(float* __restrict__ out) {
    __shared__ double sm[1024];
    const int tid = threadIdx.x;
    sm[tid] = g_partial[tid] + g_partial[tid + 1024];
    __syncthreads();
#pragma unroll
    for (int o = 512; o; o >>= 1) {
        if (tid < o) sm[tid] += sm[tid + o];
        __syncthreads();
    }
    if (tid == 0) {
        double L = sm[0];
        out[0] = (float)(L + 0.05 * L * L);
    }
}

// ---------------------------------------------------------------------------
extern "C" void kernel_launch(void* const* d_in, const int* in_sizes, int n_in,
                              void* d_out, int out_size) {
    const float* X    = (const float*)d_in[0];   // [8192, 512]
    const float* W    = (const float*)d_in[1];   // [8192, 64]
    const float* invl = (const float*)d_in[2];   // [64]
    float* out = (float*)d_out;

    rownorm_kernel<<<NN / 8, 256>>>(X);
    kpca_main_kernel<<<dim3(NN / BJ, NSPLIT), 256>>>(X, W);
    finalize_kernel<<<(SS * NN) / 256, 256>>>(W, invl);
    final_reduce_kernel<<<1, 1024>>>(out);
}

// round 7
// speedup vs baseline: 5.0571x; 5.0571x over previous
#include <cuda_runtime.h>
#include <cuda_bf16.h>
#include <cstdint>

// ---------------- problem constants ----------------
#define NN      8192
#define DD      512
#define SS      64
#define TILE    128
#define KC      32                 // k-chunk (floats) for MMA1 streaming
#define NCHUNK  (DD / KC)          // 16
#define NSPLIT  2                  // i-range splits
#define NT      (NN / NSPLIT / TILE)   // 32 i-tiles per CTA
#define INV2SIG 0.0009765625f      // 1/(2*512)

// ---------------- arch gating: tcgen05 is sm_103a/sm_100a-only ----------------
#if defined(__CUDA_ARCH__)
#  if defined(__CUDA_ARCH_FEAT_SM103_ALL) || defined(__CUDA_ARCH_FEAT_SM100_ALL) || \
      defined(__CUDA_ARCH_FEAT_SM101_ALL) || \
      (defined(__CUDA_ARCH_SPECIFIC__)) || (defined(__CUDA_ARCH_FAMILY_SPECIFIC__))
#    define HAS_TCGEN05 1
#  else
#    define HAS_TCGEN05 0
#  endif
#else
#  define HAS_TCGEN05 0
#endif

// ---------------- smem layout (bytes) ----------------
#define SM_TMEMPTR  0
#define SM_MB_AB0   8
#define SM_MB_AB1   16
#define SM_MB_G0    24
#define SM_MB_G1    32
#define SM_MB_E     40
#define SM_SQJ      64                    // 128 floats
#define SM_A0       1024                  // 16KB per buffer (128 x 32 f32, SW128)
#define SM_A1       (SM_A0 + 16384)
#define SM_B0       (SM_A1 + 16384)
#define SM_B1       (SM_B0 + 16384)
#define SM_KHI      (SM_B1 + 16384)       // 32KB: 2 chunks of [128j x 64i] bf16
#define SM_KLO      (SM_KHI + 32768)
#define SM_WHI      (SM_KLO + 32768)      // 16KB: 2 chunks of [64s x 64i] bf16
#define SM_WLO      (SM_WHI + 16384)
#define SM_TOTAL    (SM_WLO + 16384)      // 164864

// ---------------- TMEM layout (cols) ----------------
#define TM_D1A  0
#define TM_D1B  128
#define TM_D2   256
#define TM_COLS 512

#define SWZ(x) ((x) ^ (((x) >> 3) & 0x70))

// instruction descriptors
// MMA1: kind::tf32, dtype=F32(1), atype=btype=TF32(2), N=128, M=128
#define IDESC_MMA1 ((1u<<4) | (2u<<7) | (2u<<10) | ((128u/8u)<<17) | ((128u/16u)<<24))
// MMA2: kind::f16,  dtype=F32(1), atype=btype=BF16(1), N=64, M=128
#define IDESC_MMA2 ((1u<<4) | (1u<<7) | (1u<<10) | ((64u/8u)<<17)  | ((128u/16u)<<24))

// ---------------- scratch ----------------
__device__ float  g_sq[NN];
__device__ float  g_Epart[NSPLIT * NN * SS];   // [split][j][s]
__device__ double g_partial[2048];

// ---------------- helpers ----------------
static __device__ __forceinline__ uint32_t s2u(const void* p) {
    uint32_t a;
    asm("{ .reg .u64 t; cvta.to.shared.u64 t, %1; cvt.u32.u64 %0, t; }" : "=r"(a) : "l"(p));
    return a;
}

#if HAS_TCGEN05 || !defined(__CUDA_ARCH__)

static __device__ __forceinline__ uint32_t elect_one() {
    uint32_t pred;
    asm volatile("{\n\t.reg .pred p;\n\telect.sync _|p, 0xFFFFFFFF;\n\tselp.b32 %0, 1, 0, p;\n\t}" : "=r"(pred));
    return pred;
}

// SW128 K-major SMEM descriptor: layout=2, version=1, SBO=64, LBO=1
static __device__ __forceinline__ uint64_t mkdesc(uint32_t addr) {
    return ((uint64_t)2 << 61) | ((uint64_t)1 << 46) | ((uint64_t)64 << 32) |
           ((uint64_t)1 << 16) | (uint64_t)((addr >> 4) & 0x3FFF);
}

static __device__ __forceinline__ void mbar_init(uint32_t a, uint32_t cnt) {
    asm volatile("mbarrier.init.shared.b64 [%0], %1;" :: "r"(a), "r"(cnt) : "memory");
}

static __device__ __forceinline__ void mbar_wait(uint32_t a, uint32_t parity) {
    asm volatile(
        "{\n\t.reg .pred P;\n\t"
        "WL_%=:\n\t"
        "mbarrier.try_wait.parity.acquire.cta.shared::cta.b64 P, [%0], %1, 0x989680;\n\t"
        "@P bra.uni WD_%=;\n\t"
        "bra.uni WL_%=;\n\t"
        "WD_%=:\n\t}"
        :: "r"(a), "r"(parity) : "memory");
}

static __device__ __forceinline__ void tc_commit(uint32_t mbar) {
    asm volatile(
        "tcgen05.commit.cta_group::1.mbarrier::arrive::one.shared::cluster.b64 [%0];"
        :: "r"(mbar) : "memory");
}

static __device__ __forceinline__ void mma_tf32(uint32_t d, uint64_t a, uint64_t b,
                                                uint32_t idesc, uint32_t en) {
    asm volatile(
        "{\n\t.reg .pred p;\n\tsetp.ne.u32 p, %4, 0;\n\t"
        "tcgen05.mma.cta_group::1.kind::tf32 [%0], %1, %2, %3, {%5, %5, %5, %5}, p;\n\t}"
        :: "r"(d), "l"(a), "l"(b), "r"(idesc), "r"(en), "r"(0u) : "memory");
}

static __device__ __forceinline__ void mma_bf16(uint32_t d, uint64_t a, uint64_t b,
                                                uint32_t idesc, uint32_t en) {
    asm volatile(
        "{\n\t.reg .pred p;\n\tsetp.ne.u32 p, %4, 0;\n\t"
        "tcgen05.mma.cta_group::1.kind::f16 [%0], %1, %2, %3, {%5, %5, %5, %5}, p;\n\t}"
        :: "r"(d), "l"(a), "l"(b), "r"(idesc), "r"(en), "r"(0u) : "memory");
}

#define TC_LD_X32(r, addr) \
    asm volatile( \
        "tcgen05.ld.sync.aligned.32x32b.x32.b32 " \
        "{%0, %1, %2, %3, %4, %5, %6, %7, " \
        " %8, %9, %10, %11, %12, %13, %14, %15, " \
        " %16, %17, %18, %19, %20, %21, %22, %23, " \
        " %24, %25, %26, %27, %28, %29, %30, %31}, [%32];" \
        : "=r"((r)[0]),  "=r"((r)[1]),  "=r"((r)[2]),  "=r"((r)[3]), \
          "=r"((r)[4]),  "=r"((r)[5]),  "=r"((r)[6]),  "=r"((r)[7]), \
          "=r"((r)[8]),  "=r"((r)[9]),  "=r"((r)[10]), "=r"((r)[11]), \
          "=r"((r)[12]), "=r"((r)[13]), "=r"((r)[14]), "=r"((r)[15]), \
          "=r"((r)[16]), "=r"((r)[17]), "=r"((r)[18]), "=r"((r)[19]), \
          "=r"((r)[20]), "=r"((r)[21]), "=r"((r)[22]), "=r"((r)[23]), \
          "=r"((r)[24]), "=r"((r)[25]), "=r"((r)[26]), "=r"((r)[27]), \
          "=r"((r)[28]), "=r"((r)[29]), "=r"((r)[30]), "=r"((r)[31]) \
        : "r"(addr))

#define TC_WAIT_LD()   asm volatile("tcgen05.wait::ld.sync.aligned;" ::: "memory")
#define TC_FENCE_AFTER()  asm volatile("tcgen05.fence::after_thread_sync;" ::: "memory")
#define TC_FENCE_BEFORE() asm volatile("tcgen05.fence::before_thread_sync;" ::: "memory")
#define FENCE_ASYNC()  asm volatile("fence.proxy.async.shared::cta;" ::: "memory")

#endif // HAS_TCGEN05 helpers

// ---------------------------------------------------------------------------
// Kernel 1: row squared norms
// ---------------------------------------------------------------------------
__global__ void rownorm_kernel(const float* __restrict__ X) {
    int row  = blockIdx.x * 8 + (threadIdx.x >> 5);
    int lane = threadIdx.x & 31;
    const float4* xr = reinterpret_cast<const float4*>(X + (size_t)row * DD);
    float s = 0.f;
#pragma unroll
    for (int q = 0; q < 4; q++) {
        float4 v = xr[lane + q * 32];
        s += v.x * v.x + v.y * v.y + v.z * v.z + v.w * v.w;
    }
#pragma unroll
    for (int o = 16; o; o >>= 1) s += __shfl_xor_sync(0xFFFFFFFFu, s, o);
    if (lane == 0) g_sq[row] = s;
}

// ---------------------------------------------------------------------------
// Kernel 2: fused pipeline. grid (64 j-tiles, 2 i-splits), 256 threads.
// tcgen05 path on sm_103a; CUDA-core fallback body otherwise (only reached
// if the driver ever selects a non-arch-specific cubin).
// ---------------------------------------------------------------------------
__global__ __launch_bounds__(256, 1)
void kpca_mma_kernel(const float* __restrict__ X, const float* __restrict__ W) {
    extern __shared__ char smem[];
#if HAS_TCGEN05
    const uint32_t sb = s2u(smem);
    const int t    = threadIdx.x;
    const int wid  = t >> 5;
    const int lane = t & 31;
    const int wg   = t >> 7;          // warpgroup 0/1
    const int sub  = wid & 3;         // TMEM subpartition
    const int jt     = blockIdx.x;
    const int isplit = blockIdx.y;
    const int j0     = jt * TILE;

    // TMEM alloc (warp 0), mbarrier init (thread 0), sqj preload
    if (wid == 0) {
        asm volatile("tcgen05.alloc.cta_group::1.sync.aligned.shared::cta.b32 [%0], %1;"
                     :: "r"(sb + SM_TMEMPTR), "r"((uint32_t)TM_COLS) : "memory");
    }
    if (t == 0) {
        mbar_init(sb + SM_MB_AB0, 1);
        mbar_init(sb + SM_MB_AB1, 1);
        mbar_init(sb + SM_MB_G0, 1);
        mbar_init(sb + SM_MB_G1, 1);
        mbar_init(sb + SM_MB_E, 1);
    }
    if (t < 128) ((float*)(smem + SM_SQJ))[t] = g_sq[j0 + t];
    __syncthreads();

    uint32_t tb;
    asm volatile("ld.shared.b32 %0, [%1];" : "=r"(tb) : "r"(sb + SM_TMEMPTR));

    // chunk-load mapping: id = t + q*256; row = id>>3 (0..127), f4 = id&7
    const int lrow = t >> 3;
    const int lf4  = t & 7;

    float4 pa[4], pb[4];   // register prefetch (one chunk: 4 float4 each)

    // preload chunk 0 of tile 0
    {
        const int i0 = isplit * (NN / NSPLIT);
#pragma unroll
        for (int q = 0; q < 4; q++) {
            int row = lrow + q * 32;
            pa[q] = *reinterpret_cast<const float4*>(&X[(size_t)(i0 + row) * DD + lf4 * 4]);
            pb[q] = *reinterpret_cast<const float4*>(&X[(size_t)(j0 + row) * DD + lf4 * 4]);
        }
    }

    for (int it = 0; it <= NT; it++) {
        // ---------------- load + MMA1 phase for tile `it` ----------------
        if (it < NT) {
            const int i0 = isplit * (NN / NSPLIT) + it * TILE;
            for (int c = 0; c < NCHUNK; c++) {
                const int g = it * NCHUNK + c;
                const int b = g & 1;
                if (g >= 2) mbar_wait(sb + SM_MB_AB0 + b * 8, ((g >> 1) - 1) & 1);

                const int Aoff = SM_A0 + b * 16384;
                const int Boff = SM_B0 + b * 16384;
#pragma unroll
                for (int q = 0; q < 4; q++) {
                    int row = lrow + q * 32;
                    *reinterpret_cast<float4*>(smem + Aoff + SWZ(row * 128 + lf4 * 16)) = pa[q];
                    *reinterpret_cast<float4*>(smem + Boff + SWZ(row * 128 + lf4 * 16)) = pb[q];
                }
                FENCE_ASYNC();
                __syncthreads();

                if (wid == 0 && elect_one()) {
                    uint64_t ad = mkdesc(sb + Aoff);
                    uint64_t bd = mkdesc(sb + Boff);
                    uint32_t d1 = tb + ((it & 1) ? TM_D1B : TM_D1A);
#pragma unroll
                    for (int s = 0; s < 4; s++)
                        mma_tf32(d1, ad + s * 2, bd + s * 2, IDESC_MMA1, (c | s) != 0);
                    tc_commit(sb + SM_MB_AB0 + b * 8);
                }

                // prefetch next chunk (next c, or chunk 0 of next tile)
                if (c + 1 < NCHUNK) {
                    int kc = (c + 1) * KC;
#pragma unroll
                    for (int q = 0; q < 4; q++) {
                        int row = lrow + q * 32;
                        pa[q] = *reinterpret_cast<const float4*>(&X[(size_t)(i0 + row) * DD + kc + lf4 * 4]);
                        pb[q] = *reinterpret_cast<const float4*>(&X[(size_t)(j0 + row) * DD + kc + lf4 * 4]);
                    }
                } else if (it + 1 < NT) {
                    const int i0n = isplit * (NN / NSPLIT) + (it + 1) * TILE;
#pragma unroll
                    for (int q = 0; q < 4; q++) {
                        int row = lrow + q * 32;
                        pa[q] = *reinterpret_cast<const float4*>(&X[(size_t)(i0n + row) * DD + lf4 * 4]);
                        pb[q] = *reinterpret_cast<const float4*>(&X[(size_t)(j0 + row) * DD + lf4 * 4]);
                    }
                }
            }
            if (wid == 0 && elect_one())
                tc_commit(sb + SM_MB_G0 + (it & 1) * 8);
        }

        // ---------------- epilogue for tile `it-1` (overlaps MMA1(it)) ----
        if (it >= 1) {
            const int ite = it - 1;
            const int i0e = isplit * (NN / NSPLIT) + ite * TILE;
            const uint32_t d1 = tb + ((ite & 1) ? TM_D1B : TM_D1A);

            mbar_wait(sb + SM_MB_G0 + (ite & 1) * 8, (ite >> 1) & 1);
            TC_FENCE_AFTER();

            uint32_t r[64];
            TC_LD_X32(r,      d1 + wg * 64);
            TC_LD_X32(r + 32, d1 + wg * 64 + 32);
            TC_WAIT_LD();
            TC_FENCE_BEFORE();

            // wait until MMA2(ite-1) has consumed Kexp/W buffers
            if (ite >= 1) mbar_wait(sb + SM_MB_E, (ite - 1) & 1);

            const int   iloc = sub * 32 + lane;        // local i row (k-dim of MMA2)
            const float sqi  = g_sq[i0e + iloc];
            const int   ic   = iloc >> 6;              // k-chunk 0/1
            const int   ii2  = (iloc & 63) * 2;        // byte offset in row
            const int   KhiC = SM_KHI + ic * 16384;
            const int   KloC = SM_KLO + ic * 16384;
            const float* sqs = (const float*)(smem + SM_SQJ);

#pragma unroll
            for (int rr = 0; rr < 64; rr++) {
                int   j  = wg * 64 + rr;
                float gv = __uint_as_float(r[rr]);
                float v  = __expf(fmaf(2.f, gv, -sqi - sqs[j]) * INV2SIG);
                __nv_bfloat16 h = __float2bfloat16_rn(v);
                __nv_bfloat16 l = __float2bfloat16_rn(v - __bfloat162float(h));
                *reinterpret_cast<__nv_bfloat16*>(smem + KhiC + SWZ(j * 128 + ii2)) = h;
                *reinterpret_cast<__nv_bfloat16*>(smem + KloC + SWZ(j * 128 + ii2)) = l;
            }

            // W tile load + bf16 split + transpose into [s][i] K-major
#pragma unroll
            for (int m = 0; m < 32; m++) {
                int flat = m * 256 + t;
                int iw   = flat >> 6;
                int s    = flat & 63;
                float wv = W[(size_t)(i0e + iw) * SS + s];
                __nv_bfloat16 h = __float2bfloat16_rn(wv);
                __nv_bfloat16 l = __float2bfloat16_rn(wv - __bfloat162float(h));
                int c2 = iw >> 6;
                int sw = SWZ(s * 128 + (iw & 63) * 2);
                *reinterpret_cast<__nv_bfloat16*>(smem + SM_WHI + c2 * 8192 + sw) = h;
                *reinterpret_cast<__nv_bfloat16*>(smem + SM_WLO + c2 * 8192 + sw) = l;
            }
            FENCE_ASYNC();
            __syncthreads();

            if (wid == 0 && elect_one()) {
#pragma unroll
                for (int c2 = 0; c2 < 2; c2++) {
                    uint64_t ah = mkdesc(sb + SM_KHI + c2 * 16384);
                    uint64_t al = mkdesc(sb + SM_KLO + c2 * 16384);
                    uint64_t bh = mkdesc(sb + SM_WHI + c2 * 8192);
                    uint64_t bl = mkdesc(sb + SM_WLO + c2 * 8192);
#pragma unroll
                    for (int s = 0; s < 4; s++) {
                        uint32_t first = (ite == 0 && c2 == 0 && s == 0);
                        mma_bf16(tb + TM_D2, ah + s * 2, bh + s * 2, IDESC_MMA2, !first);
                        mma_bf16(tb + TM_D2, al + s * 2, bh + s * 2, IDESC_MMA2, 1u);
                        mma_bf16(tb + TM_D2, ah + s * 2, bl + s * 2, IDESC_MMA2, 1u);
                    }
                }
                tc_commit(sb + SM_MB_E);
            }
        }
    }

    // ---------------- final E readout ----------------
    mbar_wait(sb + SM_MB_E, (NT - 1) & 1);
    TC_FENCE_AFTER();
    {
        uint32_t e[32];
        TC_LD_X32(e, tb + TM_D2 + wg * 32);
        TC_WAIT_LD();
        TC_FENCE_BEFORE();
        int jloc = sub * 32 + lane;
        float* dst = &g_Epart[(size_t)isplit * NN * SS + (size_t)(j0 + jloc) * SS + wg * 32];
#pragma unroll
        for (int q = 0; q < 8; q++)
            reinterpret_cast<float4*>(dst)[q] =
                make_float4(__uint_as_float(e[q * 4 + 0]), __uint_as_float(e[q * 4 + 1]),
                            __uint_as_float(e[q * 4 + 2]), __uint_as_float(e[q * 4 + 3]));
    }
    __syncthreads();
    if (wid == 0) {
        asm volatile("tcgen05.relinquish_alloc_permit.cta_group::1.sync.aligned;" ::: "memory");
        asm volatile("tcgen05.dealloc.cta_group::1.sync.aligned.b32 %0, %1;"
                     :: "r"(tb), "r"((uint32_t)TM_COLS));
    }
#else
    // ---------------- CUDA-core fallback (R4-proven logic) ----------------
    float (*As)[132]  = reinterpret_cast<float(*)[132]>(smem);            // 8448 B
    float (*Bs)[132]  = reinterpret_cast<float(*)[132]>(smem + 8448);     // 8448 B
    float (*Ksm)[132] = reinterpret_cast<float(*)[132]>(smem + 16896);    // 16896 B
    float (*Wsm)[64]  = reinterpret_cast<float(*)[64]>(smem + 33792);     // 8192 B

    const int jt     = blockIdx.x;
    const int isplit = blockIdx.y;
    const int j0     = jt * TILE;
    const int t  = threadIdx.x;
    const int tx = t & 15;
    const int ty = t >> 4;

    float Ereg[4][8];
#pragma unroll
    for (int v = 0; v < 4; v++)
#pragma unroll
        for (int u = 0; u < 8; u++) Ereg[v][u] = 0.f;

    float sqj[8];
#pragma unroll
    for (int u = 0; u < 8; u++) sqj[u] = g_sq[j0 + tx * 8 + u];

    const int lr  = t >> 2;
    const int lc4 = (t & 3) * 4;

    for (int it = 0; it < NT; it++) {
        const int i0 = isplit * (NN / NSPLIT) + it * TILE;

        float acc[8][8];
#pragma unroll
        for (int u = 0; u < 8; u++)
#pragma unroll
            for (int v = 0; v < 8; v++) acc[u][v] = 0.f;

        for (int kc = 0; kc < DD; kc += 16) {
            float4 av0 = *reinterpret_cast<const float4*>(&X[(size_t)(i0 + lr)      * DD + kc + lc4]);
            float4 av1 = *reinterpret_cast<const float4*>(&X[(size_t)(i0 + lr + 64) * DD + kc + lc4]);
            float4 bv0 = *reinterpret_cast<const float4*>(&X[(size_t)(j0 + lr)      * DD + kc + lc4]);
            float4 bv1 = *reinterpret_cast<const float4*>(&X[(size_t)(j0 + lr + 64) * DD + kc + lc4]);

            __syncthreads();
            As[lc4 + 0][lr] = av0.x;  As[lc4 + 1][lr] = av0.y;
            As[lc4 + 2][lr] = av0.z;  As[lc4 + 3][lr] = av0.w;
            As[lc4 + 0][lr + 64] = av1.x;  As[lc4 + 1][lr + 64] = av1.y;
            As[lc4 + 2][lr + 64] = av1.z;  As[lc4 + 3][lr + 64] = av1.w;
            Bs[lc4 + 0][lr] = bv0.x;  Bs[lc4 + 1][lr] = bv0.y;
            Bs[lc4 + 2][lr] = bv0.z;  Bs[lc4 + 3][lr] = bv0.w;
            Bs[lc4 + 0][lr + 64] = bv1.x;  Bs[lc4 + 1][lr + 64] = bv1.y;
            Bs[lc4 + 2][lr + 64] = bv1.z;  Bs[lc4 + 3][lr + 64] = bv1.w;
            __syncthreads();

#pragma unroll
            for (int k = 0; k < 16; k++) {
                float4 a0 = *reinterpret_cast<const float4*>(&As[k][ty * 8]);
                float4 a1 = *reinterpret_cast<const float4*>(&As[k][ty * 8 + 4]);
                float4 b0 = *reinterpret_cast<const float4*>(&Bs[k][tx * 8]);
                float4 b1 = *reinterpret_cast<const float4*>(&Bs[k][tx * 8 + 4]);
                float a[8] = {a0.x, a0.y, a0.z, a0.w, a1.x, a1.y, a1.z, a1.w};
                float b[8] = {b0.x, b0.y, b0.z, b0.w, b1.x, b1.y, b1.z, b1.w};
#pragma unroll
                for (int u = 0; u < 8; u++)
#pragma unroll
                    for (int v = 0; v < 8; v++)
                        acc[u][v] = fmaf(a[u], b[v], acc[u][v]);
            }
        }

        float sqi[8];
#pragma unroll
        for (int u = 0; u < 8; u++) sqi[u] = g_sq[i0 + ty * 8 + u];
#pragma unroll
        for (int u = 0; u < 8; u++)
#pragma unroll
            for (int v = 0; v < 8; v++)
                acc[u][v] = __expf((2.f * acc[u][v] - sqi[u] - sqj[v]) * INV2SIG);

        const int wr = t >> 3;
        const int wc = (t & 7) * 8;
        for (int c = 0; c < 4; c++) {
            __syncthreads();
            if ((ty >> 2) == c) {
                const int tyl = ty & 3;
#pragma unroll
                for (int u = 0; u < 8; u++) {
                    *reinterpret_cast<float4*>(&Ksm[tyl * 8 + u][tx * 8]) =
                        make_float4(acc[u][0], acc[u][1], acc[u][2], acc[u][3]);
                    *reinterpret_cast<float4*>(&Ksm[tyl * 8 + u][tx * 8 + 4]) =
                        make_float4(acc[u][4], acc[u][5], acc[u][6], acc[u][7]);
                }
            }
            {
                const float* wp = &W[(size_t)(i0 + c * 32 + wr) * SS + wc];
                *reinterpret_cast<float4*>(&Wsm[wr][wc])     = *reinterpret_cast<const float4*>(wp);
                *reinterpret_cast<float4*>(&Wsm[wr][wc + 4]) = *reinterpret_cast<const float4*>(wp + 4);
            }
            __syncthreads();

#pragma unroll
            for (int ii = 0; ii < 32; ii++) {
                float4 w4 = *reinterpret_cast<const float4*>(&Wsm[ii][ty * 4]);
                float4 k0 = *reinterpret_cast<const float4*>(&Ksm[ii][tx * 8]);
                float4 k1 = *reinterpret_cast<const float4*>(&Ksm[ii][tx * 8 + 4]);
                float w[4] = {w4.x, w4.y, w4.z, w4.w};
                float kk[8] = {k0.x, k0.y, k0.z, k0.w, k1.x, k1.y, k1.z, k1.w};
#pragma unroll
                for (int v = 0; v < 4; v++)
#pragma unroll
                    for (int u = 0; u < 8; u++)
                        Ereg[v][u] = fmaf(w[v], kk[u], Ereg[v][u]);
            }
        }
    }

    // scatter to [split][j][s]
#pragma unroll
    for (int v = 0; v < 4; v++)
#pragma unroll
        for (int u = 0; u < 8; u++)
            g_Epart[(size_t)isplit * NN * SS + (size_t)(j0 + tx * 8 + u) * SS + (ty * 4 + v)] = Ereg[v][u];
#endif
}

// ---------------------------------------------------------------------------
// Kernel 3: combine E partials -> per-element loss contribution -> block reduce
// Epart layout: [split][j][s]
// ---------------------------------------------------------------------------
__global__ void finalize_kernel(const float* __restrict__ W,
                                const float* __restrict__ invl) {
    const int tid = threadIdx.x;
    const int idx = blockIdx.x * 256 + tid;   // 0..524287
    const int j = idx >> 6;
    const int s = idx & 63;

    float E = g_Epart[idx] + g_Epart[NN * SS + idx];

    double Ed = (double)E;
    double contrib = 0.5 * Ed * ((double)W[(size_t)j * SS + s] - (double)invl[s] * Ed);

    __shared__ double sm[256];
    sm[tid] = contrib;
    __syncthreads();
#pragma unroll
    for (int o = 128; o; o >>= 1) {
        if (tid < o) sm[tid] += sm[tid + o];
        __syncthreads();
    }
    if (tid == 0) g_partial[blockIdx.x] = sm[0];
}

// ---------------------------------------------------------------------------
// Kernel 4: final reduction + nonlinearity
// ---------------------------------------------------------------------------
__global__ void final_reduce_kernel(float* __restrict__ out) {
    __shared__ double sm[1024];
    const int tid = threadIdx.x;
    sm[tid] = g_partial[tid] + g_partial[tid + 1024];
    __syncthreads();
#pragma unroll
    for (int o = 512; o; o >>= 1) {
        if (tid < o) sm[tid] += sm[tid + o];
        __syncthreads();
    }
    if (tid == 0) {
        double L = sm[0];
        out[0] = (float)(L + 0.05 * L * L);
    }
}

// ---------------------------------------------------------------------------
extern "C" void kernel_launch(void* const* d_in, const int* in_sizes, int n_in,
                              void* d_out, int out_size) {
    const float* X    = (const float*)d_in[0];   // [8192, 512]
    const float* W    = (const float*)d_in[1];   // [8192, 64]
    const float* invl = (const float*)d_in[2];   // [64]
    float* out = (float*)d_out;

    cudaFuncSetAttribute(kpca_mma_kernel,
                         cudaFuncAttributeMaxDynamicSharedMemorySize, SM_TOTAL);

    rownorm_kernel<<<NN / 8, 256>>>(X);
    kpca_mma_kernel<<<dim3(NN / TILE, NSPLIT), 256, SM_TOTAL>>>(X, W);
    finalize_kernel<<<(NN * SS) / 256, 256>>>(W, invl);
    final_reduce_kernel<<<1, 1024>>>(out);
}

// round 8
// speedup vs baseline: 7.3797x; 1.4593x over previous
#include <cuda_runtime.h>
#include <cuda_bf16.h>
#include <cstdint>

// ---------------- problem constants ----------------
#define NN      8192
#define DD      512
#define SS      64
#define TILE    128
#define NCHUNK  16                 // k-chunks per tile (32 floats each)
#define NSPLIT  2
#define NT      (NN / NSPLIT / TILE)   // 32 i-tiles per CTA
#define NTG     (NN / TILE)            // 64 global tiles
#define NCH_TOT (NT * NCHUNK)          // 512 chunks per CTA
#define STAGES  3
#define INV2SIG 0.0009765625f      // 1/(2*512)

// ---------------- arch gating ----------------
#if defined(__CUDA_ARCH__)
#  if defined(__CUDA_ARCH_FEAT_SM103_ALL) || defined(__CUDA_ARCH_FEAT_SM100_ALL) || \
      defined(__CUDA_ARCH_FEAT_SM101_ALL) || \
      (defined(__CUDA_ARCH_SPECIFIC__)) || (defined(__CUDA_ARCH_FAMILY_SPECIFIC__))
#    define HAS_TCGEN05 1
#  else
#    define HAS_TCGEN05 0
#  endif
#else
#  define HAS_TCGEN05 0
#endif

// ---------------- smem layout (bytes) ----------------
#define SM_TMEMPTR   0
#define MB_ABF(s)    (64  + (s) * 8)      // AB full  [3]
#define MB_ABE(s)    (88  + (s) * 8)      // AB empty [3]
#define MB_GF(b)     (112 + (b) * 8)      // G full   [2]
#define MB_GC        128                  // G consumed (count=4)
#define MB_WF(b)     (136 + (b) * 8)      // W full   [2]
#define MB_E         152                  // MMA2 done
#define SM_SQJ       512                  // 128 floats
#define SM_AB        1024                 // stage s: A @ +s*32768, B @ +s*32768+16384
#define SM_KHI       (SM_AB + STAGES * 32768)        // 99328, 2 x 16KB
#define SM_KLO       (SM_KHI + 32768)                // 132096
#define SM_W         (SM_KLO + 32768)                // 164864, 2 x 32KB (hi 16KB + lo 16KB)
#define SM_TOTAL     (SM_W + 2 * 32768)              // 230400

// ---------------- TMEM layout (cols) ----------------
#define TM_D1A  0
#define TM_D1B  128
#define TM_D2   256
#define TM_COLS 512

#define SWZ(x) ((x) ^ (((x) >> 3) & 0x70))

// MMA1: kind::tf32, dtype=F32(1), atype=btype=TF32(2), N=128, M=128
#define IDESC_MMA1 ((1u<<4) | (2u<<7) | (2u<<10) | ((128u/8u)<<17) | ((128u/16u)<<24))
// MMA2: kind::f16,  dtype=F32(1), atype=btype=BF16(1), N=64, M=128
#define IDESC_MMA2 ((1u<<4) | (1u<<7) | (1u<<10) | ((64u/8u)<<17)  | ((128u/16u)<<24))

// ---------------- scratch ----------------
__device__ float  g_sq[NN];
__device__ float  g_Epart[NSPLIT * NN * SS];              // [split][j][s]
__device__ double g_partial[2048];
__device__ __align__(1024) char g_Xpk[NTG * NCHUNK * 16384];   // 16 MB swizzled X chunk images
__device__ __align__(1024) char g_Wpk[NTG * 32768];            // 2 MB  swizzled W hi/lo images

// ---------------- helpers ----------------
static __device__ __forceinline__ uint32_t s2u(const void* p) {
    uint32_t a;
    asm("{ .reg .u64 t; cvta.to.shared.u64 t, %1; cvt.u32.u64 %0, t; }" : "=r"(a) : "l"(p));
    return a;
}

#if HAS_TCGEN05 || !defined(__CUDA_ARCH__)

// SW128 K-major SMEM descriptor: layout=2, version=1, SBO=64, LBO=1
static __device__ __forceinline__ uint64_t mkdesc(uint32_t addr) {
    return ((uint64_t)2 << 61) | ((uint64_t)1 << 46) | ((uint64_t)64 << 32) |
           ((uint64_t)1 << 16) | (uint64_t)((addr >> 4) & 0x3FFF);
}

static __device__ __forceinline__ void mbar_init(uint32_t a, uint32_t cnt) {
    asm volatile("mbarrier.init.shared.b64 [%0], %1;" :: "r"(a), "r"(cnt) : "memory");
}
static __device__ __forceinline__ void mbar_arrive(uint32_t a) {
    asm volatile("mbarrier.arrive.shared.b64 _, [%0];" :: "r"(a) : "memory");
}
static __device__ __forceinline__ void mbar_expect_tx(uint32_t a, uint32_t bytes) {
    asm volatile("mbarrier.arrive.expect_tx.shared.b64 _, [%0], %1;"
                 :: "r"(a), "r"(bytes) : "memory");
}
static __device__ __forceinline__ void mbar_wait(uint32_t a, uint32_t parity) {
    asm volatile(
        "{\n\t.reg .pred P;\n\t"
        "WL_%=:\n\t"
        "mbarrier.try_wait.parity.acquire.cta.shared::cta.b64 P, [%0], %1, 0x989680;\n\t"
        "@P bra.uni WD_%=;\n\t"
        "bra.uni WL_%=;\n\t"
        "WD_%=:\n\t}"
        :: "r"(a), "r"(parity) : "memory");
}
static __device__ __forceinline__ void bulk_cp(uint32_t dst, const void* src,
                                               uint32_t bytes, uint32_t mbar) {
    asm volatile(
        "cp.async.bulk.shared::cluster.global.mbarrier::complete_tx::bytes "
        "[%0], [%1], %2, [%3];"
        :: "r"(dst), "l"(src), "r"(bytes), "r"(mbar) : "memory");
}
static __device__ __forceinline__ void tc_commit(uint32_t mbar) {
    asm volatile(
        "tcgen05.commit.cta_group::1.mbarrier::arrive::one.shared::cluster.b64 [%0];"
        :: "r"(mbar) : "memory");
}
static __device__ __forceinline__ void mma_tf32(uint32_t d, uint64_t a, uint64_t b,
                                                uint32_t idesc, uint32_t en) {
    asm volatile(
        "{\n\t.reg .pred p;\n\tsetp.ne.u32 p, %4, 0;\n\t"
        "tcgen05.mma.cta_group::1.kind::tf32 [%0], %1, %2, %3, {%5, %5, %5, %5}, p;\n\t}"
        :: "r"(d), "l"(a), "l"(b), "r"(idesc), "r"(en), "r"(0u) : "memory");
}
static __device__ __forceinline__ void mma_bf16(uint32_t d, uint64_t a, uint64_t b,
                                                uint32_t idesc, uint32_t en) {
    asm volatile(
        "{\n\t.reg .pred p;\n\tsetp.ne.u32 p, %4, 0;\n\t"
        "tcgen05.mma.cta_group::1.kind::f16 [%0], %1, %2, %3, {%5, %5, %5, %5}, p;\n\t}"
        :: "r"(d), "l"(a), "l"(b), "r"(idesc), "r"(en), "r"(0u) : "memory");
}

#define TC_LD_X32(r, addr) \
    asm volatile( \
        "tcgen05.ld.sync.aligned.32x32b.x32.b32 " \
        "{%0, %1, %2, %3, %4, %5, %6, %7, " \
        " %8, %9, %10, %11, %12, %13, %14, %15, " \
        " %16, %17, %18, %19, %20, %21, %22, %23, " \
        " %24, %25, %26, %27, %28, %29, %30, %31}, [%32];" \
        : "=r"((r)[0]),  "=r"((r)[1]),  "=r"((r)[2]),  "=r"((r)[3]), \
          "=r"((r)[4]),  "=r"((r)[5]),  "=r"((r)[6]),  "=r"((r)[7]), \
          "=r"((r)[8]),  "=r"((r)[9]),  "=r"((r)[10]), "=r"((r)[11]), \
          "=r"((r)[12]), "=r"((r)[13]), "=r"((r)[14]), "=r"((r)[15]), \
          "=r"((r)[16]), "=r"((r)[17]), "=r"((r)[18]), "=r"((r)[19]), \
          "=r"((r)[20]), "=r"((r)[21]), "=r"((r)[22]), "=r"((r)[23]), \
          "=r"((r)[24]), "=r"((r)[25]), "=r"((r)[26]), "=r"((r)[27]), \
          "=r"((r)[28]), "=r"((r)[29]), "=r"((r)[30]), "=r"((r)[31]) \
        : "r"(addr))

#define TC_WAIT_LD()      asm volatile("tcgen05.wait::ld.sync.aligned;" ::: "memory")
#define TC_FENCE_AFTER()  asm volatile("tcgen05.fence::after_thread_sync;" ::: "memory")
#define TC_FENCE_BEFORE() asm volatile("tcgen05.fence::before_thread_sync;" ::: "memory")
#define FENCE_ASYNC()     asm volatile("fence.proxy.async.shared::cta;" ::: "memory")

#endif // helpers

// ---------------------------------------------------------------------------
// Kernel 1: row squared norms
// ---------------------------------------------------------------------------
__global__ void rownorm_kernel(const float* __restrict__ X) {
    int row  = blockIdx.x * 8 + (threadIdx.x >> 5);
    int lane = threadIdx.x & 31;
    const float4* xr = reinterpret_cast<const float4*>(X + (size_t)row * DD);
    float s = 0.f;
#pragma unroll
    for (int q = 0; q < 4; q++) {
        float4 v = xr[lane + q * 32];
        s += v.x * v.x + v.y * v.y + v.z * v.z + v.w * v.w;
    }
#pragma unroll
    for (int o = 16; o; o >>= 1) s += __shfl_xor_sync(0xFFFFFFFFu, s, o);
    if (lane == 0) g_sq[row] = s;
}

// ---------------------------------------------------------------------------
// Kernel 1b: pack X into swizzled 16KB chunk images (ready for bulk copy)
// grid (64 tiles, 16 chunks) x 256
// ---------------------------------------------------------------------------
__global__ void xpack_kernel(const float* __restrict__ X) {
    const int gt = blockIdx.x, c = blockIdx.y;
    const int t = threadIdx.x;
    const int row0 = t >> 3, f4 = t & 7;
    char* out = g_Xpk + ((size_t)gt * NCHUNK + c) * 16384;
#pragma unroll
    for (int q = 0; q < 4; q++) {
        int row = row0 + q * 32;
        float4 v = *reinterpret_cast<const float4*>(
            &X[(size_t)(gt * TILE + row) * DD + c * 32 + f4 * 4]);
        *reinterpret_cast<float4*>(out + SWZ(row * 128 + f4 * 16)) = v;
    }
}

// ---------------------------------------------------------------------------
// Kernel 1c: pack W into per-tile bf16 hi/lo swizzled 32KB images
// grid 64 x 256
// ---------------------------------------------------------------------------
__global__ void wpack_kernel(const float* __restrict__ W) {
    const int gt = blockIdx.x;
    const int t = threadIdx.x;
    char* out = g_Wpk + (size_t)gt * 32768;
#pragma unroll
    for (int m = 0; m < 32; m++) {
        int flat = m * 256 + t;
        int iw = flat >> 6, s = flat & 63;
        float v = W[(size_t)(gt * TILE + iw) * SS + s];
        __nv_bfloat16 h = __float2bfloat16_rn(v);
        __nv_bfloat16 l = __float2bfloat16_rn(v - __bfloat162float(h));
        int c2 = iw >> 6;
        int sw = SWZ(s * 128 + (iw & 63) * 2);
        *reinterpret_cast<__nv_bfloat16*>(out + c2 * 8192 + sw) = h;
        *reinterpret_cast<__nv_bfloat16*>(out + 16384 + c2 * 8192 + sw) = l;
    }
}

// ---------------------------------------------------------------------------
// Kernel 2: warp-specialized tcgen05 pipeline.
// grid (64 j-tiles, 2 i-splits), 160 threads.
//   warp 0 lane 0 : producer (bulk copies + MMA1 issue)
//   warps 1-4     : consumer (epilogue: LDTM -> exp -> bf16 split -> MMA2)
// ---------------------------------------------------------------------------
__global__ __launch_bounds__(160, 1)
void kpca_mma_kernel() {
    extern __shared__ char smem[];
#if HAS_TCGEN05
    const uint32_t sb = s2u(smem);
    const int t    = threadIdx.x;
    const int wid  = t >> 5;
    const int lane = t & 31;
    const int jt     = blockIdx.x;
    const int isplit = blockIdx.y;
    const int j0     = jt * TILE;

    if (wid == 0) {
        asm volatile("tcgen05.alloc.cta_group::1.sync.aligned.shared::cta.b32 [%0], %1;"
                     :: "r"(sb + SM_TMEMPTR), "r"((uint32_t)TM_COLS) : "memory");
    }
    if (t == 0) {
#pragma unroll
        for (int s = 0; s < STAGES; s++) { mbar_init(sb + MB_ABF(s), 1); mbar_init(sb + MB_ABE(s), 1); }
        mbar_init(sb + MB_GF(0), 1);  mbar_init(sb + MB_GF(1), 1);
        mbar_init(sb + MB_GC, 4);
        mbar_init(sb + MB_WF(0), 1);  mbar_init(sb + MB_WF(1), 1);
        mbar_init(sb + MB_E, 1);
    }
    if (t < 128) ((float*)(smem + SM_SQJ))[t] = g_sq[j0 + t];
    __syncthreads();

    uint32_t tb;
    asm volatile("ld.shared.b32 %0, [%1];" : "=r"(tb) : "r"(sb + SM_TMEMPTR));

    if (wid == 0) {
        // ================= PRODUCER (lane 0) =================
        if (lane == 0) {
            const char* xpkA = g_Xpk + (size_t)(isplit * NT) * NCHUNK * 16384;
            const char* xpkB = g_Xpk + (size_t)jt * NCHUNK * 16384;
            for (int g = 0; g < NCH_TOT + 2; g++) {
                // ---- copy issue for chunk g ----
                if (g < NCH_TOT) {
                    const int it_c = g >> 4, c_c = g & 15;
                    if (c_c == 0) {
                        // W buffer (it_c&1) free once MMA2(it_c-2) done
                        if (it_c >= 2) mbar_wait(sb + MB_E, it_c & 1);
                        mbar_expect_tx(sb + MB_WF(it_c & 1), 32768);
                        bulk_cp(sb + SM_W + (it_c & 1) * 32768,
                                g_Wpk + (size_t)(isplit * NT + it_c) * 32768,
                                32768, sb + MB_WF(it_c & 1));
                    }
                    const int s = g % STAGES;
                    if (g >= STAGES) mbar_wait(sb + MB_ABE(s), ((g / STAGES) - 1) & 1);
                    mbar_expect_tx(sb + MB_ABF(s), 32768);
                    bulk_cp(sb + SM_AB + s * 32768,
                            xpkA + ((size_t)it_c * NCHUNK + c_c) * 16384,
                            16384, sb + MB_ABF(s));
                    bulk_cp(sb + SM_AB + s * 32768 + 16384,
                            xpkB + (size_t)c_c * 16384,
                            16384, sb + MB_ABF(s));
                }
                // ---- MMA1 issue for chunk g-2 ----
                if (g >= 2) {
                    const int gm = g - 2;
                    const int it = gm >> 4, c = gm & 15, s = gm % STAGES;
                    if (c == 0 && it >= 2) mbar_wait(sb + MB_GC, it & 1);  // epi(it-2) LDTM done
                    mbar_wait(sb + MB_ABF(s), (gm / STAGES) & 1);
                    uint64_t ad = mkdesc(sb + SM_AB + s * 32768);
                    uint64_t bd = mkdesc(sb + SM_AB + s * 32768 + 16384);
                    uint32_t d1 = tb + ((it & 1) ? TM_D1B : TM_D1A);
#pragma unroll
                    for (int ss = 0; ss < 4; ss++)
                        mma_tf32(d1, ad + ss * 2, bd + ss * 2, IDESC_MMA1, (c | ss) != 0);
                    tc_commit(sb + MB_ABE(s));
                    if (c == 15) tc_commit(sb + MB_GF(it & 1));
                }
            }
        }
    } else {
        // ================= CONSUMER (warps 1-4, 128 threads) =================
        const int sub  = wid & 3;               // TMEM subpartition (1,2,3,0)
        const int iloc = sub * 32 + lane;       // i row / j row owned by this thread
        const int ic   = iloc >> 6;
        const int ii2  = (iloc & 63) * 2;
        const int KhiC = SM_KHI + ic * 16384;
        const int KloC = SM_KLO + ic * 16384;
        const float* sqs = (const float*)(smem + SM_SQJ);

        for (int ite = 0; ite < NT; ite++) {
            const uint32_t d1 = tb + ((ite & 1) ? TM_D1B : TM_D1A);
            const float sqi = g_sq[isplit * (NN / NSPLIT) + ite * TILE + iloc];

            mbar_wait(sb + MB_GF(ite & 1), (ite >> 1) & 1);
            TC_FENCE_AFTER();
            if (ite >= 1) mbar_wait(sb + MB_E, (ite - 1) & 1);   // K buffer free

#pragma unroll
            for (int p = 0; p < 2; p++) {
                uint32_t r[64];
                TC_LD_X32(r,      d1 + p * 64);
                TC_LD_X32(r + 32, d1 + p * 64 + 32);
                TC_WAIT_LD();
                if (p == 1 && lane == 0) mbar_arrive(sb + MB_GC);  // D1 WAR release
#pragma unroll
                for (int rr = 0; rr < 64; rr++) {
                    int   j  = p * 64 + rr;
                    float gv = __uint_as_float(r[rr]);
                    float v  = __expf(fmaf(2.f, gv, -sqi - sqs[j]) * INV2SIG);
                    __nv_bfloat16 h = __float2bfloat16_rn(v);
                    __nv_bfloat16 l = __float2bfloat16_rn(v - __bfloat162float(h));
                    *reinterpret_cast<__nv_bfloat16*>(smem + KhiC + SWZ(j * 128 + ii2)) = h;
                    *reinterpret_cast<__nv_bfloat16*>(smem + KloC + SWZ(j * 128 + ii2)) = l;
                }
            }
            FENCE_ASYNC();
            asm volatile("bar.sync 1, 128;" ::: "memory");

            if (t == 32) {   // warp 1 lane 0 issues MMA2
                mbar_wait(sb + MB_WF(ite & 1), (ite >> 1) & 1);
                const uint32_t wb = SM_W + (ite & 1) * 32768;
#pragma unroll
                for (int c2 = 0; c2 < 2; c2++) {
                    uint64_t ah = mkdesc(sb + SM_KHI + c2 * 16384);
                    uint64_t al = mkdesc(sb + SM_KLO + c2 * 16384);
                    uint64_t bh = mkdesc(sb + wb + c2 * 8192);
                    uint64_t bl = mkdesc(sb + wb + 16384 + c2 * 8192);
#pragma unroll
                    for (int ss = 0; ss < 4; ss++) {
                        uint32_t first = (ite == 0 && c2 == 0 && ss == 0);
                        mma_bf16(tb + TM_D2, ah + ss * 2, bh + ss * 2, IDESC_MMA2, !first);
                        mma_bf16(tb + TM_D2, al + ss * 2, bh + ss * 2, IDESC_MMA2, 1u);
                        mma_bf16(tb + TM_D2, ah + ss * 2, bl + ss * 2, IDESC_MMA2, 1u);
                    }
                }
                tc_commit(sb + MB_E);
            }
        }

        // ---------------- final E readout ----------------
        mbar_wait(sb + MB_E, (NT - 1) & 1);
        TC_FENCE_AFTER();
        {
            uint32_t e[64];
            TC_LD_X32(e,      tb + TM_D2);
            TC_LD_X32(e + 32, tb + TM_D2 + 32);
            TC_WAIT_LD();
            TC_FENCE_BEFORE();
            int jloc = sub * 32 + lane;
            float* dst = &g_Epart[(size_t)isplit * NN * SS + (size_t)(j0 + jloc) * SS];
#pragma unroll
            for (int q = 0; q < 16; q++)
                reinterpret_cast<float4*>(dst)[q] =
                    make_float4(__uint_as_float(e[q * 4 + 0]), __uint_as_float(e[q * 4 + 1]),
                                __uint_as_float(e[q * 4 + 2]), __uint_as_float(e[q * 4 + 3]));
        }
    }

    __syncthreads();
    if (wid == 0) {
        asm volatile("tcgen05.relinquish_alloc_permit.cta_group::1.sync.aligned;" ::: "memory");
        asm volatile("tcgen05.dealloc.cta_group::1.sync.aligned.b32 %0, %1;"
                     :: "r"(tb), "r"((uint32_t)TM_COLS));
    }
#else
    // non-sm_103a pass: never selected on GB300 (arch-specific cubin wins).
    (void)smem;
#endif
}

// ---------------------------------------------------------------------------
// Kernel 3: combine E partials -> per-element loss contribution -> block reduce
// ---------------------------------------------------------------------------
__global__ void finalize_kernel(const float* __restrict__ W,
                                const float* __restrict__ invl) {
    const int tid = threadIdx.x;
    const int idx = blockIdx.x * 256 + tid;   // 0..524287
    const int j = idx >> 6;
    const int s = idx & 63;

    float E = g_Epart[idx] + g_Epart[NN * SS + idx];

    double Ed = (double)E;
    double contrib = 0.5 * Ed * ((double)W[(size_t)j * SS + s] - (double)invl[s] * Ed);

    __shared__ double sm[256];
    sm[tid] = contrib;
    __syncthreads();
#pragma unroll
    for (int o = 128; o; o >>= 1) {
        if (tid < o) sm[tid] += sm[tid + o];
        __syncthreads();
    }
    if (tid == 0) g_partial[blockIdx.x] = sm[0];
}

// ---------------------------------------------------------------------------
// Kernel 4: final reduction + nonlinearity
// ---------------------------------------------------------------------------
__global__ void final_reduce_kernel(float* __restrict__ out) {
    __shared__ double sm[1024];
    const int tid = threadIdx.x;
    sm[tid] = g_partial[tid] + g_partial[tid + 1024];
    __syncthreads();
#pragma unroll
    for (int o = 512; o; o >>= 1) {
        if (tid < o) sm[tid] += sm[tid + o];
        __syncthreads();
    }
    if (tid == 0) {
        double L = sm[0];
        out[0] = (float)(L + 0.05 * L * L);
    }
}

// ---------------------------------------------------------------------------
extern "C" void kernel_launch(void* const* d_in, const int* in_sizes, int n_in,
                              void* d_out, int out_size) {
    const float* X    = (const float*)d_in[0];   // [8192, 512]
    const float* W    = (const float*)d_in[1];   // [8192, 64]
    const float* invl = (const float*)d_in[2];   // [64]
    float* out = (float*)d_out;

    cudaFuncSetAttribute(kpca_mma_kernel,
                         cudaFuncAttributeMaxDynamicSharedMemorySize, SM_TOTAL);

    rownorm_kernel<<<NN / 8, 256>>>(X);
    xpack_kernel<<<dim3(NTG, NCHUNK), 256>>>(X);
    wpack_kernel<<<NTG, 256>>>(W);
    kpca_mma_kernel<<<dim3(NTG, NSPLIT), 160, SM_TOTAL>>>();
    finalize_kernel<<<(NN * SS) / 256, 256>>>(W, invl);
    final_reduce_kernel<<<1, 1024>>>(out);
}

// round 9
// speedup vs baseline: 9.3468x; 1.2666x over previous
#include <cuda_runtime.h>
#include <cuda_bf16.h>
#include <cstdint>

// ---------------- problem constants ----------------
#define NN      8192
#define DD      512
#define SS      64
#define TILE    128
#define NCHUNK  8                  // k-chunks per tile (64 bf16 elems each)
#define NSPLIT  2
#define NT      (NN / NSPLIT / TILE)   // 32 i-tiles per CTA
#define NTG     (NN / TILE)            // 64 global tiles
#define NCH_TOT (NT * NCHUNK)          // 256 chunks per CTA
#define STAGES  3
#define INV2SIG 0.0009765625f      // 1/(2*512)

// ---------------- arch gating ----------------
#if defined(__CUDA_ARCH__)
#  if defined(__CUDA_ARCH_FEAT_SM103_ALL) || defined(__CUDA_ARCH_FEAT_SM100_ALL) || \
      defined(__CUDA_ARCH_FEAT_SM101_ALL) || \
      (defined(__CUDA_ARCH_SPECIFIC__)) || (defined(__CUDA_ARCH_FAMILY_SPECIFIC__))
#    define HAS_TCGEN05 1
#  else
#    define HAS_TCGEN05 0
#  endif
#else
#  define HAS_TCGEN05 0
#endif

// ---------------- smem layout (bytes) ----------------
#define SM_TMEMPTR   0
#define MB_ABF(s)    (64  + (s) * 8)      // AB full  [3]
#define MB_ABE(s)    (88  + (s) * 8)      // AB empty [3]
#define MB_GF(b)     (112 + (b) * 8)      // G full   [2]
#define MB_GC        128                  // G consumed (count=4)
#define MB_WF(b)     (136 + (b) * 8)      // W full   [2]
#define MB_E         152                  // MMA2 done
#define SM_SQJ       512                  // 128 floats
#define SM_AB        1024                 // stage s: A @ +s*32768, B @ +s*32768+16384
#define SM_KHI       (SM_AB + STAGES * 32768)        // 99328, 2 x 16KB
#define SM_KLO       (SM_KHI + 32768)                // 132096
#define SM_W         (SM_KLO + 32768)                // 164864, 2 x 32KB (hi 16KB + lo 16KB)
#define SM_TOTAL     (SM_W + 2 * 32768)              // 230400

// ---------------- TMEM layout (cols) ----------------
#define TM_D1A  0
#define TM_D1B  128
#define TM_D2   256
#define TM_COLS 512

#define SWZ(x) ((x) ^ (((x) >> 3) & 0x70))

// MMA1: kind::f16, dtype=F32(1), atype=btype=BF16(1), N=128, M=128
#define IDESC_MMA1 ((1u<<4) | (1u<<7) | (1u<<10) | ((128u/8u)<<17) | ((128u/16u)<<24))
// MMA2: kind::f16, dtype=F32(1), atype=btype=BF16(1), N=64,  M=128
#define IDESC_MMA2 ((1u<<4) | (1u<<7) | (1u<<10) | ((64u/8u)<<17)  | ((128u/16u)<<24))

// ---------------- scratch ----------------
__device__ float  g_sq[NN];
__device__ float  g_Epart[NSPLIT * NN * SS];              // [split][j][s]
__device__ double g_partial[2048];
__device__ __align__(1024) char g_Xpk[NTG * NCHUNK * 16384];   // 8 MB bf16 swizzled X chunk images
__device__ __align__(1024) char g_Wpk[NTG * 32768];            // 2 MB  swizzled W hi/lo images

// ---------------- helpers ----------------
static __device__ __forceinline__ uint32_t s2u(const void* p) {
    uint32_t a;
    asm("{ .reg .u64 t; cvta.to.shared.u64 t, %1; cvt.u32.u64 %0, t; }" : "=r"(a) : "l"(p));
    return a;
}

#if HAS_TCGEN05 || !defined(__CUDA_ARCH__)

// SW128 K-major SMEM descriptor: layout=2, version=1, SBO=64, LBO=1
static __device__ __forceinline__ uint64_t mkdesc(uint32_t addr) {
    return ((uint64_t)2 << 61) | ((uint64_t)1 << 46) | ((uint64_t)64 << 32) |
           ((uint64_t)1 << 16) | (uint64_t)((addr >> 4) & 0x3FFF);
}

static __device__ __forceinline__ void mbar_init(uint32_t a, uint32_t cnt) {
    asm volatile("mbarrier.init.shared.b64 [%0], %1;" :: "r"(a), "r"(cnt) : "memory");
}
static __device__ __forceinline__ void mbar_arrive(uint32_t a) {
    asm volatile("mbarrier.arrive.shared.b64 _, [%0];" :: "r"(a) : "memory");
}
static __device__ __forceinline__ void mbar_expect_tx(uint32_t a, uint32_t bytes) {
    asm volatile("mbarrier.arrive.expect_tx.shared.b64 _, [%0], %1;"
                 :: "r"(a), "r"(bytes) : "memory");
}
static __device__ __forceinline__ void mbar_wait(uint32_t a, uint32_t parity) {
    asm volatile(
        "{\n\t.reg .pred P;\n\t"
        "WL_%=:\n\t"
        "mbarrier.try_wait.parity.acquire.cta.shared::cta.b64 P, [%0], %1, 0x989680;\n\t"
        "@P bra.uni WD_%=;\n\t"
        "bra.uni WL_%=;\n\t"
        "WD_%=:\n\t}"
        :: "r"(a), "r"(parity) : "memory");
}
static __device__ __forceinline__ void bulk_cp(uint32_t dst, const void* src,
                                               uint32_t bytes, uint32_t mbar) {
    asm volatile(
        "cp.async.bulk.shared::cluster.global.mbarrier::complete_tx::bytes "
        "[%0], [%1], %2, [%3];"
        :: "r"(dst), "l"(src), "r"(bytes), "r"(mbar) : "memory");
}
static __device__ __forceinline__ void tc_commit(uint32_t mbar) {
    asm volatile(
        "tcgen05.commit.cta_group::1.mbarrier::arrive::one.shared::cluster.b64 [%0];"
        :: "r"(mbar) : "memory");
}
static __device__ __forceinline__ void mma_bf16(uint32_t d, uint64_t a, uint64_t b,
                                                uint32_t idesc, uint32_t en) {
    asm volatile(
        "{\n\t.reg .pred p;\n\tsetp.ne.u32 p, %4, 0;\n\t"
        "tcgen05.mma.cta_group::1.kind::f16 [%0], %1, %2, %3, {%5, %5, %5, %5}, p;\n\t}"
        :: "r"(d), "l"(a), "l"(b), "r"(idesc), "r"(en), "r"(0u) : "memory");
}

#define TC_LD_X32(r, addr) \
    asm volatile( \
        "tcgen05.ld.sync.aligned.32x32b.x32.b32 " \
        "{%0, %1, %2, %3, %4, %5, %6, %7, " \
        " %8, %9, %10, %11, %12, %13, %14, %15, " \
        " %16, %17, %18, %19, %20, %21, %22, %23, " \
        " %24, %25, %26, %27, %28, %29, %30, %31}, [%32];" \
        : "=r"((r)[0]),  "=r"((r)[1]),  "=r"((r)[2]),  "=r"((r)[3]), \
          "=r"((r)[4]),  "=r"((r)[5]),  "=r"((r)[6]),  "=r"((r)[7]), \
          "=r"((r)[8]),  "=r"((r)[9]),  "=r"((r)[10]), "=r"((r)[11]), \
          "=r"((r)[12]), "=r"((r)[13]), "=r"((r)[14]), "=r"((r)[15]), \
          "=r"((r)[16]), "=r"((r)[17]), "=r"((r)[18]), "=r"((r)[19]), \
          "=r"((r)[20]), "=r"((r)[21]), "=r"((r)[22]), "=r"((r)[23]), \
          "=r"((r)[24]), "=r"((r)[25]), "=r"((r)[26]), "=r"((r)[27]), \
          "=r"((r)[28]), "=r"((r)[29]), "=r"((r)[30]), "=r"((r)[31]) \
        : "r"(addr))

#define TC_WAIT_LD()      asm volatile("tcgen05.wait::ld.sync.aligned;" ::: "memory")
#define TC_FENCE_AFTER()  asm volatile("tcgen05.fence::after_thread_sync;" ::: "memory")
#define TC_FENCE_BEFORE() asm volatile("tcgen05.fence::before_thread_sync;" ::: "memory")
#define FENCE_ASYNC()     asm volatile("fence.proxy.async.shared::cta;" ::: "memory")

#endif // helpers

// ---------------------------------------------------------------------------
// Kernel 1: row squared norms (exact fp32 X)
// ---------------------------------------------------------------------------
__global__ void rownorm_kernel(const float* __restrict__ X) {
    int row  = blockIdx.x * 8 + (threadIdx.x >> 5);
    int lane = threadIdx.x & 31;
    const float4* xr = reinterpret_cast<const float4*>(X + (size_t)row * DD);
    float s = 0.f;
#pragma unroll
    for (int q = 0; q < 4; q++) {
        float4 v = xr[lane + q * 32];
        s += v.x * v.x + v.y * v.y + v.z * v.z + v.w * v.w;
    }
#pragma unroll
    for (int o = 16; o; o >>= 1) s += __shfl_xor_sync(0xFFFFFFFFu, s, o);
    if (lane == 0) g_sq[row] = s;
}

// ---------------------------------------------------------------------------
// Kernel 1b: pack X into bf16 swizzled 16KB chunk images
// grid (64 tiles, 8 chunks) x 128 threads; thread = one row of 64 values.
// ---------------------------------------------------------------------------
__global__ void xpack_kernel(const float* __restrict__ X) {
    const int gt = blockIdx.x, c = blockIdx.y;
    const int row = threadIdx.x;
    const float* src = &X[(size_t)(gt * TILE + row) * DD + c * 64];
    char* out = g_Xpk + ((size_t)gt * NCHUNK + c) * 16384;
#pragma unroll
    for (int u = 0; u < 8; u++) {     // 8 groups of 8 values -> 16B each
        float4 a = *reinterpret_cast<const float4*>(src + u * 8);
        float4 b = *reinterpret_cast<const float4*>(src + u * 8 + 4);
        __nv_bfloat162 p0 = __floats2bfloat162_rn(a.x, a.y);
        __nv_bfloat162 p1 = __floats2bfloat162_rn(a.z, a.w);
        __nv_bfloat162 p2 = __floats2bfloat162_rn(b.x, b.y);
        __nv_bfloat162 p3 = __floats2bfloat162_rn(b.z, b.w);
        uint4 v;
        v.x = *reinterpret_cast<uint32_t*>(&p0);
        v.y = *reinterpret_cast<uint32_t*>(&p1);
        v.z = *reinterpret_cast<uint32_t*>(&p2);
        v.w = *reinterpret_cast<uint32_t*>(&p3);
        *reinterpret_cast<uint4*>(out + SWZ(row * 128 + u * 16)) = v;
    }
}

// ---------------------------------------------------------------------------
// Kernel 1c: pack W into per-tile bf16 hi/lo swizzled 32KB images
// ---------------------------------------------------------------------------
__global__ void wpack_kernel(const float* __restrict__ W) {
    const int gt = blockIdx.x;
    const int t = threadIdx.x;
    char* out = g_Wpk + (size_t)gt * 32768;
#pragma unroll
    for (int m = 0; m < 32; m++) {
        int flat = m * 256 + t;
        int iw = flat >> 6, s = flat & 63;
        float v = W[(size_t)(gt * TILE + iw) * SS + s];
        __nv_bfloat16 h = __float2bfloat16_rn(v);
        __nv_bfloat16 l = __float2bfloat16_rn(v - __bfloat162float(h));
        int c2 = iw >> 6;
        int sw = SWZ(s * 128 + (iw & 63) * 2);
        *reinterpret_cast<__nv_bfloat16*>(out + c2 * 8192 + sw) = h;
        *reinterpret_cast<__nv_bfloat16*>(out + 16384 + c2 * 8192 + sw) = l;
    }
}

// ---------------------------------------------------------------------------
// Kernel 2: warp-specialized tcgen05 pipeline (bf16 MMA1).
// grid (64 j-tiles, 2 i-splits), 160 threads.
// ---------------------------------------------------------------------------
__global__ __launch_bounds__(160, 1)
void kpca_mma_kernel() {
    extern __shared__ char smem[];
#if HAS_TCGEN05
    const uint32_t sb = s2u(smem);
    const int t    = threadIdx.x;
    const int wid  = t >> 5;
    const int lane = t & 31;
    const int jt     = blockIdx.x;
    const int isplit = blockIdx.y;
    const int j0     = jt * TILE;

    if (wid == 0) {
        asm volatile("tcgen05.alloc.cta_group::1.sync.aligned.shared::cta.b32 [%0], %1;"
                     :: "r"(sb + SM_TMEMPTR), "r"((uint32_t)TM_COLS) : "memory");
    }
    if (t == 0) {
#pragma unroll
        for (int s = 0; s < STAGES; s++) { mbar_init(sb + MB_ABF(s), 1); mbar_init(sb + MB_ABE(s), 1); }
        mbar_init(sb + MB_GF(0), 1);  mbar_init(sb + MB_GF(1), 1);
        mbar_init(sb + MB_GC, 4);
        mbar_init(sb + MB_WF(0), 1);  mbar_init(sb + MB_WF(1), 1);
        mbar_init(sb + MB_E, 1);
    }
    if (t < 128) ((float*)(smem + SM_SQJ))[t] = g_sq[j0 + t];
    __syncthreads();

    uint32_t tb;
    asm volatile("ld.shared.b32 %0, [%1];" : "=r"(tb) : "r"(sb + SM_TMEMPTR));

    if (wid == 0) {
        // ================= PRODUCER (lane 0) =================
        if (lane == 0) {
            const char* xpkA = g_Xpk + (size_t)(isplit * NT) * NCHUNK * 16384;
            const char* xpkB = g_Xpk + (size_t)jt * NCHUNK * 16384;
            for (int g = 0; g < NCH_TOT + 2; g++) {
                // ---- copy issue for chunk g ----
                if (g < NCH_TOT) {
                    const int it_c = g >> 3, c_c = g & 7;
                    if (c_c == 0) {
                        if (it_c >= 2) mbar_wait(sb + MB_E, it_c & 1);
                        mbar_expect_tx(sb + MB_WF(it_c & 1), 32768);
                        bulk_cp(sb + SM_W + (it_c & 1) * 32768,
                                g_Wpk + (size_t)(isplit * NT + it_c) * 32768,
                                32768, sb + MB_WF(it_c & 1));
                    }
                    const int s = g % STAGES;
                    if (g >= STAGES) mbar_wait(sb + MB_ABE(s), ((g / STAGES) - 1) & 1);
                    mbar_expect_tx(sb + MB_ABF(s), 32768);
                    bulk_cp(sb + SM_AB + s * 32768,
                            xpkA + ((size_t)it_c * NCHUNK + c_c) * 16384,
                            16384, sb + MB_ABF(s));
                    bulk_cp(sb + SM_AB + s * 32768 + 16384,
                            xpkB + (size_t)c_c * 16384,
                            16384, sb + MB_ABF(s));
                }
                // ---- MMA1 issue for chunk g-2 ----
                if (g >= 2) {
                    const int gm = g - 2;
                    const int it = gm >> 3, c = gm & 7, s = gm % STAGES;
                    if (c == 0 && it >= 2) mbar_wait(sb + MB_GC, it & 1);  // epi(it-2) LDTM done
                    mbar_wait(sb + MB_ABF(s), (gm / STAGES) & 1);
                    uint64_t ad = mkdesc(sb + SM_AB + s * 32768);
                    uint64_t bd = mkdesc(sb + SM_AB + s * 32768 + 16384);
                    uint32_t d1 = tb + ((it & 1) ? TM_D1B : TM_D1A);
#pragma unroll
                    for (int ss = 0; ss < 4; ss++)
                        mma_bf16(d1, ad + ss * 2, bd + ss * 2, IDESC_MMA1, (c | ss) != 0);
                    tc_commit(sb + MB_ABE(s));
                    if (c == 7) tc_commit(sb + MB_GF(it & 1));
                }
            }
        }
    } else {
        // ================= CONSUMER (warps 1-4, 128 threads) =================
        const int sub  = wid & 3;               // TMEM subpartition
        const int iloc = sub * 32 + lane;       // i row owned by this thread
        const int ic   = iloc >> 6;
        const int ii2  = (iloc & 63) * 2;
        const int KhiC = SM_KHI + ic * 16384;
        const int KloC = SM_KLO + ic * 16384;
        const float* sqs = (const float*)(smem + SM_SQJ);

        for (int ite = 0; ite < NT; ite++) {
            const uint32_t d1 = tb + ((ite & 1) ? TM_D1B : TM_D1A);
            const float sqi = g_sq[isplit * (NN / NSPLIT) + ite * TILE + iloc];

            mbar_wait(sb + MB_GF(ite & 1), (ite >> 1) & 1);
            TC_FENCE_AFTER();
            if (ite >= 1) mbar_wait(sb + MB_E, (ite - 1) & 1);   // K buffer free

#pragma unroll
            for (int p = 0; p < 2; p++) {
                uint32_t r[64];
                TC_LD_X32(r,      d1 + p * 64);
                TC_LD_X32(r + 32, d1 + p * 64 + 32);
                TC_WAIT_LD();
                if (p == 1 && lane == 0) mbar_arrive(sb + MB_GC);  // D1 WAR release
#pragma unroll
                for (int rr = 0; rr < 64; rr++) {
                    int   j  = p * 64 + rr;
                    float gv = __uint_as_float(r[rr]);
                    float v  = __expf(fmaf(2.f, gv, -sqi - sqs[j]) * INV2SIG);
                    __nv_bfloat16 h = __float2bfloat16_rn(v);
                    __nv_bfloat16 l = __float2bfloat16_rn(v - __bfloat162float(h));
                    *reinterpret_cast<__nv_bfloat16*>(smem + KhiC + SWZ(j * 128 + ii2)) = h;
                    *reinterpret_cast<__nv_bfloat16*>(smem + KloC + SWZ(j * 128 + ii2)) = l;
                }
            }
            FENCE_ASYNC();
            asm volatile("bar.sync 1, 128;" ::: "memory");

            if (t == 32) {   // warp 1 lane 0 issues MMA2
                mbar_wait(sb + MB_WF(ite & 1), (ite >> 1) & 1);
                const uint32_t wb = SM_W + (ite & 1) * 32768;
#pragma unroll
                for (int c2 = 0; c2 < 2; c2++) {
                    uint64_t ah = mkdesc(sb + SM_KHI + c2 * 16384);
                    uint64_t al = mkdesc(sb + SM_KLO + c2 * 16384);
                    uint64_t bh = mkdesc(sb + wb + c2 * 8192);
                    uint64_t bl = mkdesc(sb + wb + 16384 + c2 * 8192);
#pragma unroll
                    for (int ss = 0; ss < 4; ss++) {
                        uint32_t first = (ite == 0 && c2 == 0 && ss == 0);
                        mma_bf16(tb + TM_D2, ah + ss * 2, bh + ss * 2, IDESC_MMA2, !first);
                        mma_bf16(tb + TM_D2, al + ss * 2, bh + ss * 2, IDESC_MMA2, 1u);
                        mma_bf16(tb + TM_D2, ah + ss * 2, bl + ss * 2, IDESC_MMA2, 1u);
                    }
                }
                tc_commit(sb + MB_E);
            }
        }

        // ---------------- final E readout ----------------
        mbar_wait(sb + MB_E, (NT - 1) & 1);
        TC_FENCE_AFTER();
        {
            uint32_t e[64];
            TC_LD_X32(e,      tb + TM_D2);
            TC_LD_X32(e + 32, tb + TM_D2 + 32);
            TC_WAIT_LD();
            TC_FENCE_BEFORE();
            int jloc = sub * 32 + lane;
            float* dst = &g_Epart[(size_t)isplit * NN * SS + (size_t)(j0 + jloc) * SS];
#pragma unroll
            for (int q = 0; q < 16; q++)
                reinterpret_cast<float4*>(dst)[q] =
                    make_float4(__uint_as_float(e[q * 4 + 0]), __uint_as_float(e[q * 4 + 1]),
                                __uint_as_float(e[q * 4 + 2]), __uint_as_float(e[q * 4 + 3]));
        }
    }

    __syncthreads();
    if (wid == 0) {
        asm volatile("tcgen05.relinquish_alloc_permit.cta_group::1.sync.aligned;" ::: "memory");
        asm volatile("tcgen05.dealloc.cta_group::1.sync.aligned.b32 %0, %1;"
                     :: "r"(tb), "r"((uint32_t)TM_COLS));
    }
#else
    (void)smem;
#endif
}

// ---------------------------------------------------------------------------
// Kernel 3: combine E partials -> per-element loss contribution -> block reduce
// ---------------------------------------------------------------------------
__global__ void finalize_kernel(const float* __restrict__ W,
                                const float* __restrict__ invl) {
    const int tid = threadIdx.x;
    const int idx = blockIdx.x * 256 + tid;   // 0..524287
    const int j = idx >> 6;
    const int s = idx & 63;

    float E = g_Epart[idx] + g_Epart[NN * SS + idx];

    double Ed = (double)E;
    double contrib = 0.5 * Ed * ((double)W[(size_t)j * SS + s] - (double)invl[s] * Ed);

    __shared__ double sm[256];
    sm[tid] = contrib;
    __syncthreads();
#pragma unroll
    for (int o = 128; o; o >>= 1) {
        if (tid < o) sm[tid] += sm[tid + o];
        __syncthreads();
    }
    if (tid == 0) g_partial[blockIdx.x] = sm[0];
}

// ---------------------------------------------------------------------------
// Kernel 4: final reduction + nonlinearity
// ---------------------------------------------------------------------------
__global__ void final_reduce_kernel(float* __restrict__ out) {
    __shared__ double sm[1024];
    const int tid = threadIdx.x;
    sm[tid] = g_partial[tid] + g_partial[tid + 1024];
    __syncthreads();
#pragma unroll
    for (int o = 512; o; o >>= 1) {
        if (tid < o) sm[tid] += sm[tid + o];
        __syncthreads();
    }
    if (tid == 0) {
        double L = sm[0];
        out[0] = (float)(L + 0.05 * L * L);
    }
}

// ---------------------------------------------------------------------------
extern "C" void kernel_launch(void* const* d_in, const int* in_sizes, int n_in,
                              void* d_out, int out_size) {
    const float* X    = (const float*)d_in[0];   // [8192, 512]
    const float* W    = (const float*)d_in[1];   // [8192, 64]
    const float* invl = (const float*)d_in[2];   // [64]
    float* out = (float*)d_out;

    cudaFuncSetAttribute(kpca_mma_kernel,
                         cudaFuncAttributeMaxDynamicSharedMemorySize, SM_TOTAL);

    rownorm_kernel<<<NN / 8, 256>>>(X);
    xpack_kernel<<<dim3(NTG, NCHUNK), 128>>>(X);
    wpack_kernel<<<NTG, 256>>>(W);
    kpca_mma_kernel<<<dim3(NTG, NSPLIT), 160, SM_TOTAL>>>();
    finalize_kernel<<<(NN * SS) / 256, 256>>>(W, invl);
    final_reduce_kernel<<<1, 1024>>>(out);
}

// round 12
// speedup vs baseline: 11.3550x; 1.2149x over previous
#include <cuda_runtime.h>
#include <cuda_bf16.h>
#include <cstdint>

// ---------------- problem constants ----------------
#define NN      8192
#define DD      512
#define SS      64
#define TILE    128
#define NCHUNK  8                  // k-chunks per tile (64 bf16 elems each)
#define NSPLIT  2
#define NT      (NN / NSPLIT / TILE)   // 32 i-tiles per CTA
#define NTG     (NN / TILE)            // 64 global tiles
#define NCH_TOT (NT * NCHUNK)          // 256 chunks per CTA
#define STAGES  3
#define INV2SIG 0.0009765625f      // 1/(2*512)

// ---------------- arch gating ----------------
#if defined(__CUDA_ARCH__)
#  if defined(__CUDA_ARCH_FEAT_SM103_ALL) || defined(__CUDA_ARCH_FEAT_SM100_ALL) || \
      defined(__CUDA_ARCH_FEAT_SM101_ALL) || \
      (defined(__CUDA_ARCH_SPECIFIC__)) || (defined(__CUDA_ARCH_FAMILY_SPECIFIC__))
#    define HAS_TCGEN05 1
#  else
#    define HAS_TCGEN05 0
#  endif
#else
#  define HAS_TCGEN05 0
#endif

// ---------------- smem layout (bytes) ----------------
#define SM_TMEMPTR   0
#define MB_ABF(s)    (64  + (s) * 8)      // AB full  [3]
#define MB_ABE(s)    (88  + (s) * 8)      // AB empty [3]
#define MB_GF(b)     (112 + (b) * 8)      // G full   [2]
#define MB_GC        128                  // G consumed (count=4)
#define MB_WF(b)     (136 + (b) * 8)      // W full   [2]
#define MB_E         152                  // MMA2 done
#define SM_SQJ       512                  // 128 floats
#define SM_AB        1024                 // stage s: A @ +s*32768, B @ +s*32768+16384
#define SM_KHI       (SM_AB + STAGES * 32768)        // 99328: 2 x 16KB k-chunks (bf16 K)
#define SM_W         (SM_KHI + 32768)                // 132096: 2 x 32KB (hi 16KB + lo 16KB)
#define SM_TOTAL     (SM_W + 2 * 32768)              // 197632

// ---------------- TMEM layout (cols) ----------------
#define TM_D1A  0
#define TM_D1B  128
#define TM_D2   256
#define TM_COLS 512

#define SWZ(x) ((x) ^ (((x) >> 3) & 0x70))

// MMA1: kind::f16, dtype=F32(1), atype=btype=BF16(1), N=128, M=128
#define IDESC_MMA1 ((1u<<4) | (1u<<7) | (1u<<10) | ((128u/8u)<<17) | ((128u/16u)<<24))
// MMA2: kind::f16, dtype=F32(1), atype=btype=BF16(1), N=64,  M=128
#define IDESC_MMA2 ((1u<<4) | (1u<<7) | (1u<<10) | ((64u/8u)<<17)  | ((128u/16u)<<24))

// ---------------- scratch ----------------
__device__ float  g_sq[NN];
__device__ float  g_Epart[NSPLIT * NN * SS];              // [split][j][s]
__device__ double g_partial[2048];
__device__ __align__(1024) char g_Xpk[NTG * NCHUNK * 16384];   // 8 MB bf16 swizzled X chunks
__device__ __align__(1024) char g_Wpk[NTG * 32768];            // 2 MB  swizzled W hi/lo images

// ---------------- helpers ----------------
static __device__ __forceinline__ uint32_t s2u(const void* p) {
    uint32_t a;
    asm("{ .reg .u64 t; cvta.to.shared.u64 t, %1; cvt.u32.u64 %0, t; }" : "=r"(a) : "l"(p));
    return a;
}

#if HAS_TCGEN05 || !defined(__CUDA_ARCH__)

// SW128 K-major SMEM descriptor: layout=2, version=1, SBO=64, LBO=1
static __device__ __forceinline__ uint64_t mkdesc(uint32_t addr) {
    return ((uint64_t)2 << 61) | ((uint64_t)1 << 46) | ((uint64_t)64 << 32) |
           ((uint64_t)1 << 16) | (uint64_t)((addr >> 4) & 0x3FFF);
}

static __device__ __forceinline__ void mbar_init(uint32_t a, uint32_t cnt) {
    asm volatile("mbarrier.init.shared.b64 [%0], %1;" :: "r"(a), "r"(cnt) : "memory");
}
static __device__ __forceinline__ void mbar_arrive(uint32_t a) {
    asm volatile("mbarrier.arrive.shared.b64 _, [%0];" :: "r"(a) : "memory");
}
static __device__ __forceinline__ void mbar_expect_tx(uint32_t a, uint32_t bytes) {
    asm volatile("mbarrier.arrive.expect_tx.shared.b64 _, [%0], %1;"
                 :: "r"(a), "r"(bytes) : "memory");
}
static __device__ __forceinline__ void mbar_wait(uint32_t a, uint32_t parity) {
    asm volatile(
        "{\n\t.reg .pred P;\n\t"
        "WL_%=:\n\t"
        "mbarrier.try_wait.parity.acquire.cta.shared::cta.b64 P, [%0], %1, 0x989680;\n\t"
        "@P bra.uni WD_%=;\n\t"
        "bra.uni WL_%=;\n\t"
        "WD_%=:\n\t}"
        :: "r"(a), "r"(parity) : "memory");
}
static __device__ __forceinline__ void bulk_cp(uint32_t dst, const void* src,
                                               uint32_t bytes, uint32_t mbar) {
    asm volatile(
        "cp.async.bulk.shared::cluster.global.mbarrier::complete_tx::bytes "
        "[%0], [%1], %2, [%3];"
        :: "r"(dst), "l"(src), "r"(bytes), "r"(mbar) : "memory");
}
static __device__ __forceinline__ void tc_commit(uint32_t mbar) {
    asm volatile(
        "tcgen05.commit.cta_group::1.mbarrier::arrive::one.shared::cluster.b64 [%0];"
        :: "r"(mbar) : "memory");
}
static __device__ __forceinline__ void mma_bf16(uint32_t d, uint64_t a, uint64_t b,
                                                uint32_t idesc, uint32_t en) {
    asm volatile(
        "{\n\t.reg .pred p;\n\tsetp.ne.u32 p, %4, 0;\n\t"
        "tcgen05.mma.cta_group::1.kind::f16 [%0], %1, %2, %3, {%5, %5, %5, %5}, p;\n\t}"
        :: "r"(d), "l"(a), "l"(b), "r"(idesc), "r"(en), "r"(0u) : "memory");
}

#define TC_LD_X32(r, addr) \
    asm volatile( \
        "tcgen05.ld.sync.aligned.32x32b.x32.b32 " \
        "{%0, %1, %2, %3, %4, %5, %6, %7, " \
        " %8, %9, %10, %11, %12, %13, %14, %15, " \
        " %16, %17, %18, %19, %20, %21, %22, %23, " \
        " %24, %25, %26, %27, %28, %29, %30, %31}, [%32];" \
        : "=r"((r)[0]),  "=r"((r)[1]),  "=r"((r)[2]),  "=r"((r)[3]), \
          "=r"((r)[4]),  "=r"((r)[5]),  "=r"((r)[6]),  "=r"((r)[7]), \
          "=r"((r)[8]),  "=r"((r)[9]),  "=r"((r)[10]), "=r"((r)[11]), \
          "=r"((r)[12]), "=r"((r)[13]), "=r"((r)[14]), "=r"((r)[15]), \
          "=r"((r)[16]), "=r"((r)[17]), "=r"((r)[18]), "=r"((r)[19]), \
          "=r"((r)[20]), "=r"((r)[21]), "=r"((r)[22]), "=r"((r)[23]), \
          "=r"((r)[24]), "=r"((r)[25]), "=r"((r)[26]), "=r"((r)[27]), \
          "=r"((r)[28]), "=r"((r)[29]), "=r"((r)[30]), "=r"((r)[31]) \
        : "r"(addr))

#define TC_WAIT_LD()      asm volatile("tcgen05.wait::ld.sync.aligned;" ::: "memory")
#define TC_FENCE_AFTER()  asm volatile("tcgen05.fence::after_thread_sync;" ::: "memory")
#define TC_FENCE_BEFORE() asm volatile("tcgen05.fence::before_thread_sync;" ::: "memory")
#define FENCE_ASYNC()     asm volatile("fence.proxy.async.shared::cta;" ::: "memory")

#endif // helpers

// ---------------------------------------------------------------------------
// Kernel 1: row squared norms (exact fp32 X)
// ---------------------------------------------------------------------------
__global__ void rownorm_kernel(const float* __restrict__ X) {
    int row  = blockIdx.x * 8 + (threadIdx.x >> 5);
    int lane = threadIdx.x & 31;
    const float4* xr = reinterpret_cast<const float4*>(X + (size_t)row * DD);
    float s = 0.f;
#pragma unroll
    for (int q = 0; q < 4; q++) {
        float4 v = xr[lane + q * 32];
        s += v.x * v.x + v.y * v.y + v.z * v.z + v.w * v.w;
    }
#pragma unroll
    for (int o = 16; o; o >>= 1) s += __shfl_xor_sync(0xFFFFFFFFu, s, o);
    if (lane == 0) g_sq[row] = s;
}

// ---------------------------------------------------------------------------
// Kernel 1b: pack X into bf16 swizzled 16KB chunk images
// ---------------------------------------------------------------------------
__global__ void xpack_kernel(const float* __restrict__ X) {
    const int gt = blockIdx.x, c = blockIdx.y;
    const int row = threadIdx.x;
    const float* src = &X[(size_t)(gt * TILE + row) * DD + c * 64];
    char* out = g_Xpk + ((size_t)gt * NCHUNK + c) * 16384;
#pragma unroll
    for (int u = 0; u < 8; u++) {
        float4 a = *reinterpret_cast<const float4*>(src + u * 8);
        float4 b = *reinterpret_cast<const float4*>(src + u * 8 + 4);
        __nv_bfloat162 p0 = __floats2bfloat162_rn(a.x, a.y);
        __nv_bfloat162 p1 = __floats2bfloat162_rn(a.z, a.w);
        __nv_bfloat162 p2 = __floats2bfloat162_rn(b.x, b.y);
        __nv_bfloat162 p3 = __floats2bfloat162_rn(b.z, b.w);
        uint4 v;
        v.x = *reinterpret_cast<uint32_t*>(&p0);
        v.y = *reinterpret_cast<uint32_t*>(&p1);
        v.z = *reinterpret_cast<uint32_t*>(&p2);
        v.w = *reinterpret_cast<uint32_t*>(&p3);
        *reinterpret_cast<uint4*>(out + SWZ(row * 128 + u * 16)) = v;
    }
}

// ---------------------------------------------------------------------------
// Kernel 1c: pack W into per-tile bf16 hi/lo swizzled 32KB images
// ---------------------------------------------------------------------------
__global__ void wpack_kernel(const float* __restrict__ W) {
    const int gt = blockIdx.x;
    const int t = threadIdx.x;
    char* out = g_Wpk + (size_t)gt * 32768;
#pragma unroll
    for (int m = 0; m < 32; m++) {
        int flat = m * 256 + t;
        int iw = flat >> 6, s = flat & 63;
        float v = W[(size_t)(gt * TILE + iw) * SS + s];
        __nv_bfloat16 h = __float2bfloat16_rn(v);
        __nv_bfloat16 l = __float2bfloat16_rn(v - __bfloat162float(h));
        int c2 = iw >> 6;
        int sw = SWZ(s * 128 + (iw & 63) * 2);
        *reinterpret_cast<__nv_bfloat16*>(out + c2 * 8192 + sw) = h;
        *reinterpret_cast<__nv_bfloat16*>(out + 16384 + c2 * 8192 + sw) = l;
    }
}

// ---------------------------------------------------------------------------
// Kernel 2: warp-specialized tcgen05 pipeline (R9 topology, no-KLO epilogue).
// grid (64 j-tiles, 2 i-splits), 160 threads.
//   warp 0 lane 0 : producer (bulk copies + MMA1 issue)
//   warps 1-4     : consumer (LDTM -> exp -> bf16 -> STS K -> MMA2)
// ---------------------------------------------------------------------------
__global__ __launch_bounds__(160, 1)
void kpca_mma_kernel() {
    extern __shared__ char smem[];
#if HAS_TCGEN05
    const uint32_t sb = s2u(smem);
    const int t    = threadIdx.x;
    const int wid  = t >> 5;
    const int lane = t & 31;
    const int jt     = blockIdx.x;
    const int isplit = blockIdx.y;
    const int j0     = jt * TILE;

    if (wid == 0) {
        asm volatile("tcgen05.alloc.cta_group::1.sync.aligned.shared::cta.b32 [%0], %1;"
                     :: "r"(sb + SM_TMEMPTR), "r"((uint32_t)TM_COLS) : "memory");
    }
    if (t == 0) {
#pragma unroll
        for (int s = 0; s < STAGES; s++) { mbar_init(sb + MB_ABF(s), 1); mbar_init(sb + MB_ABE(s), 1); }
        mbar_init(sb + MB_GF(0), 1);  mbar_init(sb + MB_GF(1), 1);
        mbar_init(sb + MB_GC, 4);
        mbar_init(sb + MB_WF(0), 1);  mbar_init(sb + MB_WF(1), 1);
        mbar_init(sb + MB_E, 1);
    }
    if (t < 128) ((float*)(smem + SM_SQJ))[t] = g_sq[j0 + t];
    __syncthreads();

    uint32_t tb;
    asm volatile("ld.shared.b32 %0, [%1];" : "=r"(tb) : "r"(sb + SM_TMEMPTR));

    if (wid == 0) {
        // ================= PRODUCER (lane 0) — R9-identical =================
        if (lane == 0) {
            const char* xpkA = g_Xpk + (size_t)(isplit * NT) * NCHUNK * 16384;
            const char* xpkB = g_Xpk + (size_t)jt * NCHUNK * 16384;
            for (int g = 0; g < NCH_TOT + 2; g++) {
                // ---- copy issue for chunk g ----
                if (g < NCH_TOT) {
                    const int it_c = g >> 3, c_c = g & 7;
                    if (c_c == 0) {
                        if (it_c >= 2) mbar_wait(sb + MB_E, it_c & 1);
                        mbar_expect_tx(sb + MB_WF(it_c & 1), 32768);
                        bulk_cp(sb + SM_W + (it_c & 1) * 32768,
                                g_Wpk + (size_t)(isplit * NT + it_c) * 32768,
                                32768, sb + MB_WF(it_c & 1));
                    }
                    const int s = g % STAGES;
                    if (g >= STAGES) mbar_wait(sb + MB_ABE(s), ((g / STAGES) - 1) & 1);
                    mbar_expect_tx(sb + MB_ABF(s), 32768);
                    bulk_cp(sb + SM_AB + s * 32768,
                            xpkA + ((size_t)it_c * NCHUNK + c_c) * 16384,
                            16384, sb + MB_ABF(s));
                    bulk_cp(sb + SM_AB + s * 32768 + 16384,
                            xpkB + (size_t)c_c * 16384,
                            16384, sb + MB_ABF(s));
                }
                // ---- MMA1 issue for chunk g-2 ----
                if (g >= 2) {
                    const int gm = g - 2;
                    const int it = gm >> 3, c = gm & 7, s = gm % STAGES;
                    if (c == 0 && it >= 2) mbar_wait(sb + MB_GC, it & 1);  // epi(it-2) LDTM done
                    mbar_wait(sb + MB_ABF(s), (gm / STAGES) & 1);
                    uint64_t ad = mkdesc(sb + SM_AB + s * 32768);
                    uint64_t bd = mkdesc(sb + SM_AB + s * 32768 + 16384);
                    uint32_t d1 = tb + ((it & 1) ? TM_D1B : TM_D1A);
#pragma unroll
                    for (int ss = 0; ss < 4; ss++)
                        mma_bf16(d1, ad + ss * 2, bd + ss * 2, IDESC_MMA1, (c | ss) != 0);
                    tc_commit(sb + MB_ABE(s));
                    if (c == 7) tc_commit(sb + MB_GF(it & 1));
                }
            }
        }
    } else {
        // ========== CONSUMER (warps 1-4, 128 threads) — R9 topology ==========
        const int sub  = wid & 3;               // TMEM subpartition
        const int iloc = sub * 32 + lane;       // i row owned by this thread
        const int ic   = iloc >> 6;             // k-chunk of MMA2
        const int ii2  = (iloc & 63) * 2;       // byte offset in K row
        const int KhiC = SM_KHI + ic * 16384;
        const float* sqs = (const float*)(smem + SM_SQJ);

        for (int ite = 0; ite < NT; ite++) {
            const uint32_t d1 = tb + ((ite & 1) ? TM_D1B : TM_D1A);
            const float sqi = g_sq[isplit * (NN / NSPLIT) + ite * TILE + iloc];

            mbar_wait(sb + MB_GF(ite & 1), (ite >> 1) & 1);
            TC_FENCE_AFTER();
            if (ite >= 1) mbar_wait(sb + MB_E, (ite - 1) & 1);   // K buffer free

#pragma unroll
            for (int p = 0; p < 2; p++) {
                uint32_t r[64];
                TC_LD_X32(r,      d1 + p * 64);
                TC_LD_X32(r + 32, d1 + p * 64 + 32);
                TC_WAIT_LD();
                if (p == 1 && lane == 0) mbar_arrive(sb + MB_GC);  // D1 WAR release
#pragma unroll
                for (int rr = 0; rr < 64; rr++) {
                    int   j  = p * 64 + rr;
                    float gv = __uint_as_float(r[rr]);
                    float v  = __expf(fmaf(2.f, gv, -sqi - sqs[j]) * INV2SIG);
                    *reinterpret_cast<__nv_bfloat16*>(smem + KhiC + SWZ(j * 128 + ii2)) =
                        __float2bfloat16_rn(v);
                }
            }
            FENCE_ASYNC();
            asm volatile("bar.sync 1, 128;" ::: "memory");

            if (t == 32) {   // warp 1 lane 0 issues MMA2
                mbar_wait(sb + MB_WF(ite & 1), (ite >> 1) & 1);
                const uint32_t wb = SM_W + (ite & 1) * 32768;
#pragma unroll
                for (int c2 = 0; c2 < 2; c2++) {
                    uint64_t ah = mkdesc(sb + SM_KHI + c2 * 16384);
                    uint64_t bh = mkdesc(sb + wb + c2 * 8192);
                    uint64_t bl = mkdesc(sb + wb + 16384 + c2 * 8192);
#pragma unroll
                    for (int ss = 0; ss < 4; ss++) {
                        uint32_t first = (ite == 0 && c2 == 0 && ss == 0);
                        mma_bf16(tb + TM_D2, ah + ss * 2, bh + ss * 2, IDESC_MMA2, !first);
                        mma_bf16(tb + TM_D2, ah + ss * 2, bl + ss * 2, IDESC_MMA2, 1u);
                    }
                }
                tc_commit(sb + MB_E);
            }
        }

        // ---------------- final E readout ----------------
        mbar_wait(sb + MB_E, (NT - 1) & 1);
        TC_FENCE_AFTER();
        {
            uint32_t e[64];
            TC_LD_X32(e,      tb + TM_D2);
            TC_LD_X32(e + 32, tb + TM_D2 + 32);
            TC_WAIT_LD();
            TC_FENCE_BEFORE();
            float* dst = &g_Epart[(size_t)isplit * NN * SS + (size_t)(j0 + iloc) * SS];
#pragma unroll
            for (int q = 0; q < 16; q++)
                reinterpret_cast<float4*>(dst)[q] =
                    make_float4(__uint_as_float(e[q * 4 + 0]), __uint_as_float(e[q * 4 + 1]),
                                __uint_as_float(e[q * 4 + 2]), __uint_as_float(e[q * 4 + 3]));
        }
    }

    __syncthreads();
    if (wid == 0) {
        asm volatile("tcgen05.relinquish_alloc_permit.cta_group::1.sync.aligned;" ::: "memory");
        asm volatile("tcgen05.dealloc.cta_group::1.sync.aligned.b32 %0, %1;"
                     :: "r"(tb), "r"((uint32_t)TM_COLS));
    }
#else
    (void)smem;
#endif
}

// ---------------------------------------------------------------------------
// Kernel 3: combine E partials -> per-element loss contribution -> block reduce
// ---------------------------------------------------------------------------
__global__ void finalize_kernel(const float* __restrict__ W,
                                const float* __restrict__ invl) {
    const int tid = threadIdx.x;
    const int idx = blockIdx.x * 256 + tid;   // 0..524287
    const int j = idx >> 6;
    const int s = idx & 63;

    float E = g_Epart[idx] + g_Epart[NN * SS + idx];

    double Ed = (double)E;
    double contrib = 0.5 * Ed * ((double)W[(size_t)j * SS + s] - (double)invl[s] * Ed);

    __shared__ double sm[256];
    sm[tid] = contrib;
    __syncthreads();
#pragma unroll
    for (int o = 128; o; o >>= 1) {
        if (tid < o) sm[tid] += sm[tid + o];
        __syncthreads();
    }
    if (tid == 0) g_partial[blockIdx.x] = sm[0];
}

// ---------------------------------------------------------------------------
// Kernel 4: final reduction + nonlinearity
// ---------------------------------------------------------------------------
__global__ void final_reduce_kernel(float* __restrict__ out) {
    __shared__ double sm[1024];
    const int tid = threadIdx.x;
    sm[tid] = g_partial[tid] + g_partial[tid + 1024];
    __syncthreads();
#pragma unroll
    for (int o = 512; o; o >>= 1) {
        if (tid < o) sm[tid] += sm[tid + o];
        __syncthreads();
    }
    if (tid == 0) {
        double L = sm[0];
        out[0] = (float)(L + 0.05 * L * L);
    }
}

// ---------------------------------------------------------------------------
extern "C" void kernel_launch(void* const* d_in, const int* in_sizes, int n_in,
                              void* d_out, int out_size) {
    const float* X    = (const float*)d_in[0];   // [8192, 512]
    const float* W    = (const float*)d_in[1];   // [8192, 64]
    const float* invl = (const float*)d_in[2];   // [64]
    float* out = (float*)d_out;

    cudaFuncSetAttribute(kpca_mma_kernel,
                         cudaFuncAttributeMaxDynamicSharedMemorySize, SM_TOTAL);

    rownorm_kernel<<<NN / 8, 256>>>(X);
    xpack_kernel<<<dim3(NTG, NCHUNK), 128>>>(X);
    wpack_kernel<<<NTG, 256>>>(W);
    kpca_mma_kernel<<<dim3(NTG, NSPLIT), 160, SM_TOTAL>>>();
    finalize_kernel<<<(NN * SS) / 256, 256>>>(W, invl);
    final_reduce_kernel<<<1, 1024>>>(out);
}

// round 14
// speedup vs baseline: 11.4628x; 1.0095x over previous
#include <cuda_runtime.h>
#include <cuda_bf16.h>
#include <cstdint>

// ---------------- problem constants ----------------
#define NN      8192
#define DD      512
#define SS      64
#define TILE    128
#define NCHUNK  8                  // k-chunks per tile (64 bf16 elems each)
#define NSPLIT  2
#define NT      (NN / NSPLIT / TILE)   // 32 i-tiles per CTA
#define NTG     (NN / TILE)            // 64 global tiles
#define NCH_TOT (NT * NCHUNK)          // 256 chunks per CTA
#define STAGES  3
#define INV2SIG 0.0009765625f      // 1/(2*512)

// ---------------- arch gating ----------------
#if defined(__CUDA_ARCH__)
#  if defined(__CUDA_ARCH_FEAT_SM103_ALL) || defined(__CUDA_ARCH_FEAT_SM100_ALL) || \
      defined(__CUDA_ARCH_FEAT_SM101_ALL) || \
      (defined(__CUDA_ARCH_SPECIFIC__)) || (defined(__CUDA_ARCH_FAMILY_SPECIFIC__))
#    define HAS_TCGEN05 1
#  else
#    define HAS_TCGEN05 0
#  endif
#else
#  define HAS_TCGEN05 0
#endif

// ---------------- smem layout (bytes) ----------------
#define SM_TMEMPTR   0
#define MB_ABF(s)    (64  + (s) * 8)      // AB full  [3]
#define MB_ABE(s)    (88  + (s) * 8)      // AB empty [3]
#define MB_GF(b)     (112 + (b) * 8)      // G full   [2]
#define MB_GC        128                  // G consumed (count=4)
#define MB_WF(b)     (136 + (b) * 8)      // W full   [2]
#define MB_EB(b)     (152 + (b) * 8)      // MMA2 done, per K/W parity class [2]
#define SM_SQJ       512                  // 128 floats
#define SM_AB        1024                 // stage s: A @ +s*32768, B @ +s*32768+16384
#define SM_KHI       (SM_AB + STAGES * 32768)        // 99328: 2 buffers x (2 x 16KB k-chunks)
#define SM_W         (SM_KHI + 2 * 32768)            // 164864: 2 x 32KB (hi 16KB + lo 16KB)
#define SM_TOTAL     (SM_W + 2 * 32768)              // 230400 (launchable, proven in R8)

// ---------------- TMEM layout (cols) ----------------
#define TM_D1A  0
#define TM_D1B  128
#define TM_D2   256
#define TM_COLS 512

#define SWZ(x) ((x) ^ (((x) >> 3) & 0x70))

// MMA1: kind::f16, dtype=F32(1), atype=btype=BF16(1), N=128, M=128
#define IDESC_MMA1 ((1u<<4) | (1u<<7) | (1u<<10) | ((128u/8u)<<17) | ((128u/16u)<<24))
// MMA2: kind::f16, dtype=F32(1), atype=btype=BF16(1), N=64,  M=128
#define IDESC_MMA2 ((1u<<4) | (1u<<7) | (1u<<10) | ((64u/8u)<<17)  | ((128u/16u)<<24))

// ---------------- scratch ----------------
__device__ float  g_sq[NN];
__device__ float  g_Epart[NSPLIT * NN * SS];              // [split][j][s]
__device__ double g_partial[2048];
__device__ __align__(1024) char g_Xpk[NTG * NCHUNK * 16384];   // 8 MB bf16 swizzled X chunks
__device__ __align__(1024) char g_Wpk[NTG * 32768];            // 2 MB  swizzled W hi/lo images

// ---------------- helpers ----------------
static __device__ __forceinline__ uint32_t s2u(const void* p) {
    uint32_t a;
    asm("{ .reg .u64 t; cvta.to.shared.u64 t, %1; cvt.u32.u64 %0, t; }" : "=r"(a) : "l"(p));
    return a;
}

#if HAS_TCGEN05 || !defined(__CUDA_ARCH__)

// SW128 K-major SMEM descriptor: layout=2, version=1, SBO=64, LBO=1
static __device__ __forceinline__ uint64_t mkdesc(uint32_t addr) {
    return ((uint64_t)2 << 61) | ((uint64_t)1 << 46) | ((uint64_t)64 << 32) |
           ((uint64_t)1 << 16) | (uint64_t)((addr >> 4) & 0x3FFF);
}

static __device__ __forceinline__ void mbar_init(uint32_t a, uint32_t cnt) {
    asm volatile("mbarrier.init.shared.b64 [%0], %1;" :: "r"(a), "r"(cnt) : "memory");
}
static __device__ __forceinline__ void mbar_arrive(uint32_t a) {
    asm volatile("mbarrier.arrive.shared.b64 _, [%0];" :: "r"(a) : "memory");
}
static __device__ __forceinline__ void mbar_expect_tx(uint32_t a, uint32_t bytes) {
    asm volatile("mbarrier.arrive.expect_tx.shared.b64 _, [%0], %1;"
                 :: "r"(a), "r"(bytes) : "memory");
}
static __device__ __forceinline__ void mbar_wait(uint32_t a, uint32_t parity) {
    asm volatile(
        "{\n\t.reg .pred P;\n\t"
        "WL_%=:\n\t"
        "mbarrier.try_wait.parity.acquire.cta.shared::cta.b64 P, [%0], %1, 0x989680;\n\t"
        "@P bra.uni WD_%=;\n\t"
        "bra.uni WL_%=;\n\t"
        "WD_%=:\n\t}"
        :: "r"(a), "r"(parity) : "memory");
}
static __device__ __forceinline__ void bulk_cp(uint32_t dst, const void* src,
                                               uint32_t bytes, uint32_t mbar) {
    asm volatile(
        "cp.async.bulk.shared::cluster.global.mbarrier::complete_tx::bytes "
        "[%0], [%1], %2, [%3];"
        :: "r"(dst), "l"(src), "r"(bytes), "r"(mbar) : "memory");
}
static __device__ __forceinline__ void tc_commit(uint32_t mbar) {
    asm volatile(
        "tcgen05.commit.cta_group::1.mbarrier::arrive::one.shared::cluster.b64 [%0];"
        :: "r"(mbar) : "memory");
}
static __device__ __forceinline__ void mma_bf16(uint32_t d, uint64_t a, uint64_t b,
                                                uint32_t idesc, uint32_t en) {
    asm volatile(
        "{\n\t.reg .pred p;\n\tsetp.ne.u32 p, %4, 0;\n\t"
        "tcgen05.mma.cta_group::1.kind::f16 [%0], %1, %2, %3, {%5, %5, %5, %5}, p;\n\t}"
        :: "r"(d), "l"(a), "l"(b), "r"(idesc), "r"(en), "r"(0u) : "memory");
}

#define TC_LD_X32(r, addr) \
    asm volatile( \
        "tcgen05.ld.sync.aligned.32x32b.x32.b32 " \
        "{%0, %1, %2, %3, %4, %5, %6, %7, " \
        " %8, %9, %10, %11, %12, %13, %14, %15, " \
        " %16, %17, %18, %19, %20, %21, %22, %23, " \
        " %24, %25, %26, %27, %28, %29, %30, %31}, [%32];" \
        : "=r"((r)[0]),  "=r"((r)[1]),  "=r"((r)[2]),  "=r"((r)[3]), \
          "=r"((r)[4]),  "=r"((r)[5]),  "=r"((r)[6]),  "=r"((r)[7]), \
          "=r"((r)[8]),  "=r"((r)[9]),  "=r"((r)[10]), "=r"((r)[11]), \
          "=r"((r)[12]), "=r"((r)[13]), "=r"((r)[14]), "=r"((r)[15]), \
          "=r"((r)[16]), "=r"((r)[17]), "=r"((r)[18]), "=r"((r)[19]), \
          "=r"((r)[20]), "=r"((r)[21]), "=r"((r)[22]), "=r"((r)[23]), \
          "=r"((r)[24]), "=r"((r)[25]), "=r"((r)[26]), "=r"((r)[27]), \
          "=r"((r)[28]), "=r"((r)[29]), "=r"((r)[30]), "=r"((r)[31]) \
        : "r"(addr))

#define TC_WAIT_LD()      asm volatile("tcgen05.wait::ld.sync.aligned;" ::: "memory")
#define TC_FENCE_AFTER()  asm volatile("tcgen05.fence::after_thread_sync;" ::: "memory")
#define TC_FENCE_BEFORE() asm volatile("tcgen05.fence::before_thread_sync;" ::: "memory")
#define FENCE_ASYNC()     asm volatile("fence.proxy.async.shared::cta;" ::: "memory")

#endif // helpers

// ---------------------------------------------------------------------------
// Kernel 1: row squared norms (exact fp32 X)
// ---------------------------------------------------------------------------
__global__ void rownorm_kernel(const float* __restrict__ X) {
    int row  = blockIdx.x * 8 + (threadIdx.x >> 5);
    int lane = threadIdx.x & 31;
    const float4* xr = reinterpret_cast<const float4*>(X + (size_t)row * DD);
    float s = 0.f;
#pragma unroll
    for (int q = 0; q < 4; q++) {
        float4 v = xr[lane + q * 32];
        s += v.x * v.x + v.y * v.y + v.z * v.z + v.w * v.w;
    }
#pragma unroll
    for (int o = 16; o; o >>= 1) s += __shfl_xor_sync(0xFFFFFFFFu, s, o);
    if (lane == 0) g_sq[row] = s;
}

// ---------------------------------------------------------------------------
// Kernel 1b: pack X into bf16 swizzled 16KB chunk images
// ---------------------------------------------------------------------------
__global__ void xpack_kernel(const float* __restrict__ X) {
    const int gt = blockIdx.x, c = blockIdx.y;
    const int row = threadIdx.x;
    const float* src = &X[(size_t)(gt * TILE + row) * DD + c * 64];
    char* out = g_Xpk + ((size_t)gt * NCHUNK + c) * 16384;
#pragma unroll
    for (int u = 0; u < 8; u++) {
        float4 a = *reinterpret_cast<const float4*>(src + u * 8);
        float4 b = *reinterpret_cast<const float4*>(src + u * 8 + 4);
        __nv_bfloat162 p0 = __floats2bfloat162_rn(a.x, a.y);
        __nv_bfloat162 p1 = __floats2bfloat162_rn(a.z, a.w);
        __nv_bfloat162 p2 = __floats2bfloat162_rn(b.x, b.y);
        __nv_bfloat162 p3 = __floats2bfloat162_rn(b.z, b.w);
        uint4 v;
        v.x = *reinterpret_cast<uint32_t*>(&p0);
        v.y = *reinterpret_cast<uint32_t*>(&p1);
        v.z = *reinterpret_cast<uint32_t*>(&p2);
        v.w = *reinterpret_cast<uint32_t*>(&p3);
        *reinterpret_cast<uint4*>(out + SWZ(row * 128 + u * 16)) = v;
    }
}

// ---------------------------------------------------------------------------
// Kernel 1c: pack W into per-tile bf16 hi/lo swizzled 32KB images
// ---------------------------------------------------------------------------
__global__ void wpack_kernel(const float* __restrict__ W) {
    const int gt = blockIdx.x;
    const int t = threadIdx.x;
    char* out = g_Wpk + (size_t)gt * 32768;
#pragma unroll
    for (int m = 0; m < 32; m++) {
        int flat = m * 256 + t;
        int iw = flat >> 6, s = flat & 63;
        float v = W[(size_t)(gt * TILE + iw) * SS + s];
        __nv_bfloat16 h = __float2bfloat16_rn(v);
        __nv_bfloat16 l = __float2bfloat16_rn(v - __bfloat162float(h));
        int c2 = iw >> 6;
        int sw = SWZ(s * 128 + (iw & 63) * 2);
        *reinterpret_cast<__nv_bfloat16*>(out + c2 * 8192 + sw) = h;
        *reinterpret_cast<__nv_bfloat16*>(out + 16384 + c2 * 8192 + sw) = l;
    }
}

// ---------------------------------------------------------------------------
// Kernel 2: warp-specialized tcgen05 pipeline (K double-buffer, dual MB_E).
// grid (64 j-tiles, 2 i-splits), 160 threads.
//   warp 0 lane 0 : producer (bulk copies + MMA1 issue)
//   warps 1-4     : consumer (LDTM -> exp -> bf16 -> STS K[ite&1] -> MMA2)
// MB_EB(b): committed by MMA2 of tiles with ite&1==b (16 commits each).
// "tile x-2 done" wait = commit #(x>>1) on barrier (x&1): parity ((x>>1)+1)&1.
// Waiter has issued exactly (x>>1) batches on that barrier, so e <= target:
// pass exactly at target, block at target-1. No aliasing deadlock.
// ---------------------------------------------------------------------------
__global__ __launch_bounds__(160, 1)
void kpca_mma_kernel() {
    extern __shared__ char smem[];
#if HAS_TCGEN05
    const uint32_t sb = s2u(smem);
    const int t    = threadIdx.x;
    const int wid  = t >> 5;
    const int lane = t & 31;
    const int jt     = blockIdx.x;
    const int isplit = blockIdx.y;
    const int j0     = jt * TILE;

    if (wid == 0) {
        asm volatile("tcgen05.alloc.cta_group::1.sync.aligned.shared::cta.b32 [%0], %1;"
                     :: "r"(sb + SM_TMEMPTR), "r"((uint32_t)TM_COLS) : "memory");
    }
    if (t == 0) {
#pragma unroll
        for (int s = 0; s < STAGES; s++) { mbar_init(sb + MB_ABF(s), 1); mbar_init(sb + MB_ABE(s), 1); }
        mbar_init(sb + MB_GF(0), 1);  mbar_init(sb + MB_GF(1), 1);
        mbar_init(sb + MB_GC, 4);
        mbar_init(sb + MB_WF(0), 1);  mbar_init(sb + MB_WF(1), 1);
        mbar_init(sb + MB_EB(0), 1);  mbar_init(sb + MB_EB(1), 1);
    }
    if (t < 128) ((float*)(smem + SM_SQJ))[t] = g_sq[j0 + t];
    __syncthreads();

    uint32_t tb;
    asm volatile("ld.shared.b32 %0, [%1];" : "=r"(tb) : "r"(sb + SM_TMEMPTR));

    if (wid == 0) {
        // ================= PRODUCER (lane 0) =================
        if (lane == 0) {
            const char* xpkA = g_Xpk + (size_t)(isplit * NT) * NCHUNK * 16384;
            const char* xpkB = g_Xpk + (size_t)jt * NCHUNK * 16384;
            for (int g = 0; g < NCH_TOT + 2; g++) {
                // ---- copy issue for chunk g ----
                if (g < NCH_TOT) {
                    const int it_c = g >> 3, c_c = g & 7;
                    if (c_c == 0) {
                        // W buffer (it_c&1) free once MMA2(it_c-2) done
                        if (it_c >= 2)
                            mbar_wait(sb + MB_EB(it_c & 1), ((it_c >> 1) + 1) & 1);
                        mbar_expect_tx(sb + MB_WF(it_c & 1), 32768);
                        bulk_cp(sb + SM_W + (it_c & 1) * 32768,
                                g_Wpk + (size_t)(isplit * NT + it_c) * 32768,
                                32768, sb + MB_WF(it_c & 1));
                    }
                    const int s = g % STAGES;
                    if (g >= STAGES) mbar_wait(sb + MB_ABE(s), ((g / STAGES) - 1) & 1);
                    mbar_expect_tx(sb + MB_ABF(s), 32768);
                    bulk_cp(sb + SM_AB + s * 32768,
                            xpkA + ((size_t)it_c * NCHUNK + c_c) * 16384,
                            16384, sb + MB_ABF(s));
                    bulk_cp(sb + SM_AB + s * 32768 + 16384,
                            xpkB + (size_t)c_c * 16384,
                            16384, sb + MB_ABF(s));
                }
                // ---- MMA1 issue for chunk g-2 ----
                if (g >= 2) {
                    const int gm = g - 2;
                    const int it = gm >> 3, c = gm & 7, s = gm % STAGES;
                    if (c == 0 && it >= 2) mbar_wait(sb + MB_GC, it & 1);  // epi(it-2) LDTM done
                    mbar_wait(sb + MB_ABF(s), (gm / STAGES) & 1);
                    uint64_t ad = mkdesc(sb + SM_AB + s * 32768);
                    uint64_t bd = mkdesc(sb + SM_AB + s * 32768 + 16384);
                    uint32_t d1 = tb + ((it & 1) ? TM_D1B : TM_D1A);
#pragma unroll
                    for (int ss = 0; ss < 4; ss++)
                        mma_bf16(d1, ad + ss * 2, bd + ss * 2, IDESC_MMA1, (c | ss) != 0);
                    tc_commit(sb + MB_ABE(s));
                    if (c == 7) tc_commit(sb + MB_GF(it & 1));
                }
            }
        }
    } else {
        // ========== CONSUMER (warps 1-4, 128 threads) — K double-buffered ==========
        const int sub  = wid & 3;               // TMEM subpartition
        const int iloc = sub * 32 + lane;       // i row owned by this thread
        const int ic   = iloc >> 6;             // k-chunk of MMA2
        const int ii2  = (iloc & 63) * 2;       // byte offset in K row
        const float* sqs = (const float*)(smem + SM_SQJ);

        for (int ite = 0; ite < NT; ite++) {
            const uint32_t d1 = tb + ((ite & 1) ? TM_D1B : TM_D1A);
            const float sqi = g_sq[isplit * (NN / NSPLIT) + ite * TILE + iloc];
            const int Kbuf = SM_KHI + (ite & 1) * 32768;   // this tile's K buffer
            const int KhiC = Kbuf + ic * 16384;

            mbar_wait(sb + MB_GF(ite & 1), (ite >> 1) & 1);
            TC_FENCE_AFTER();
            // K buffer (ite&1) free once MMA2(ite-2) done
            if (ite >= 2) mbar_wait(sb + MB_EB(ite & 1), ((ite >> 1) + 1) & 1);

#pragma unroll
            for (int p = 0; p < 2; p++) {
                uint32_t r[64];
                TC_LD_X32(r,      d1 + p * 64);
                TC_LD_X32(r + 32, d1 + p * 64 + 32);
                TC_WAIT_LD();
                if (p == 1 && lane == 0) mbar_arrive(sb + MB_GC);  // D1 WAR release
#pragma unroll
                for (int rr = 0; rr < 64; rr++) {
                    int   j  = p * 64 + rr;
                    float gv = __uint_as_float(r[rr]);
                    float v  = __expf(fmaf(2.f, gv, -sqi - sqs[j]) * INV2SIG);
                    *reinterpret_cast<__nv_bfloat16*>(smem + KhiC + SWZ(j * 128 + ii2)) =
                        __float2bfloat16_rn(v);
                }
            }
            FENCE_ASYNC();
            asm volatile("bar.sync 1, 128;" ::: "memory");

            if (t == 32) {   // warp 1 lane 0 issues MMA2 on K buffer (ite&1)
                mbar_wait(sb + MB_WF(ite & 1), (ite >> 1) & 1);
                const uint32_t wb = SM_W + (ite & 1) * 32768;
#pragma unroll
                for (int c2 = 0; c2 < 2; c2++) {
                    uint64_t ah = mkdesc(sb + Kbuf + c2 * 16384);
                    uint64_t bh = mkdesc(sb + wb + c2 * 8192);
                    uint64_t bl = mkdesc(sb + wb + 16384 + c2 * 8192);
#pragma unroll
                    for (int ss = 0; ss < 4; ss++) {
                        uint32_t first = (ite == 0 && c2 == 0 && ss == 0);
                        mma_bf16(tb + TM_D2, ah + ss * 2, bh + ss * 2, IDESC_MMA2, !first);
                        mma_bf16(tb + TM_D2, ah + ss * 2, bl + ss * 2, IDESC_MMA2, 1u);
                    }
                }
                tc_commit(sb + MB_EB(ite & 1));
            }
        }

        // ---------------- final E readout ----------------
        // last MMA2 = tile NT-1 (barrier 1, commit #(NT/2)): parity ((NT>>1)+1)&1
        mbar_wait(sb + MB_EB(1), ((NT >> 1) + 1) & 1);
        TC_FENCE_AFTER();
        {
            uint32_t e[64];
            TC_LD_X32(e,      tb + TM_D2);
            TC_LD_X32(e + 32, tb + TM_D2 + 32);
            TC_WAIT_LD();
            TC_FENCE_BEFORE();
            float* dst = &g_Epart[(size_t)isplit * NN * SS + (size_t)(j0 + iloc) * SS];
#pragma unroll
            for (int q = 0; q < 16; q++)
                reinterpret_cast<float4*>(dst)[q] =
                    make_float4(__uint_as_float(e[q * 4 + 0]), __uint_as_float(e[q * 4 + 1]),
                                __uint_as_float(e[q * 4 + 2]), __uint_as_float(e[q * 4 + 3]));
        }
    }

    __syncthreads();
    if (wid == 0) {
        asm volatile("tcgen05.relinquish_alloc_permit.cta_group::1.sync.aligned;" ::: "memory");
        asm volatile("tcgen05.dealloc.cta_group::1.sync.aligned.b32 %0, %1;"
                     :: "r"(tb), "r"((uint32_t)TM_COLS));
    }
#else
    (void)smem;
#endif
}

// ---------------------------------------------------------------------------
// Kernel 3: combine E partials -> per-element loss contribution -> block reduce
// ---------------------------------------------------------------------------
__global__ void finalize_kernel(const float* __restrict__ W,
                                const float* __restrict__ invl) {
    const int tid = threadIdx.x;
    const int idx = blockIdx.x * 256 + tid;   // 0..524287
    const int j = idx >> 6;
    const int s = idx & 63;

    float E = g_Epart[idx] + g_Epart[NN * SS + idx];

    double Ed = (double)E;
    double contrib = 0.5 * Ed * ((double)W[(size_t)j * SS + s] - (double)invl[s] * Ed);

    __shared__ double sm[256];
    sm[tid] = contrib;
    __syncthreads();
#pragma unroll
    for (int o = 128; o; o >>= 1) {
        if (tid < o) sm[tid] += sm[tid + o];
        __syncthreads();
    }
    if (tid == 0) g_partial[blockIdx.x] = sm[0];
}

// ---------------------------------------------------------------------------
// Kernel 4: final reduction + nonlinearity
// ---------------------------------------------------------------------------
__global__ void final_reduce_kernel(float* __restrict__ out) {
    __shared__ double sm[1024];
    const int tid = threadIdx.x;
    sm[tid] = g_partial[tid] + g_partial[tid + 1024];
    __syncthreads();
#pragma unroll
    for (int o = 512; o; o >>= 1) {
        if (tid < o) sm[tid] += sm[tid + o];
        __syncthreads();
    }
    if (tid == 0) {
        double L = sm[0];
        out[0] = (float)(L + 0.05 * L * L);
    }
}

// ---------------------------------------------------------------------------
extern "C" void kernel_launch(void* const* d_in, const int* in_sizes, int n_in,
                              void* d_out, int out_size) {
    const float* X    = (const float*)d_in[0];   // [8192, 512]
    const float* W    = (const float*)d_in[1];   // [8192, 64]
    const float* invl = (const float*)d_in[2];   // [64]
    float* out = (float*)d_out;

    cudaFuncSetAttribute(kpca_mma_kernel,
                         cudaFuncAttributeMaxDynamicSharedMemorySize, SM_TOTAL);

    rownorm_kernel<<<NN / 8, 256>>>(X);
    xpack_kernel<<<dim3(NTG, NCHUNK), 128>>>(X);
    wpack_kernel<<<NTG, 256>>>(W);
    kpca_mma_kernel<<<dim3(NTG, NSPLIT), 160, SM_TOTAL>>>();
    finalize_kernel<<<(NN * SS) / 256, 256>>>(W, invl);
    final_reduce_kernel<<<1, 1024>>>(out);
}

// round 16
// speedup vs baseline: 12.8370x; 1.1199x over previous
#include <cuda_runtime.h>
#include <cuda_bf16.h>
#include <cstdint>

// ---------------- problem constants ----------------
#define NN      8192
#define DD      512
#define SS      64
#define TILE    128
#define NCHUNK  8                  // k-chunks per tile (64 bf16 elems each)
#define NSPLIT  2
#define NT      (NN / NSPLIT / TILE)   // 32 i-tiles per CTA
#define NTG     (NN / TILE)            // 64 global tiles
#define NCH_TOT (NT * NCHUNK)          // 256 chunks per CTA
#define STAGES  3
#define INV2SIG 0.0009765625f      // 1/(2*512)
#define LOG2E   1.4426950408889634f
#define CEXP    (INV2SIG * LOG2E)  // premultiplied exp2 constant

// ---------------- arch gating ----------------
#if defined(__CUDA_ARCH__)
#  if defined(__CUDA_ARCH_FEAT_SM103_ALL) || defined(__CUDA_ARCH_FEAT_SM100_ALL) || \
      defined(__CUDA_ARCH_FEAT_SM101_ALL) || \
      (defined(__CUDA_ARCH_SPECIFIC__)) || (defined(__CUDA_ARCH_FAMILY_SPECIFIC__))
#    define HAS_TCGEN05 1
#  else
#    define HAS_TCGEN05 0
#  endif
#else
#  define HAS_TCGEN05 0
#endif

// ---------------- smem layout (bytes) ----------------
#define SM_TMEMPTR   0
#define MB_ABF(s)    (64  + (s) * 8)      // AB full  [3]
#define MB_ABE(s)    (88  + (s) * 8)      // AB empty [3]
#define MB_GF(b)     (112 + (b) * 8)      // G full   [2]
#define MB_GC        128                  // G consumed (count=4)
#define MB_WF(b)     (136 + (b) * 8)      // W full   [2]
#define MB_EB(b)     (152 + (b) * 8)      // MMA2 done, per K/W parity class [2]
#define SM_SQJ       512                  // 128 floats (premultiplied by CEXP)
#define SM_AB        1024                 // stage s: A @ +s*32768, B @ +s*32768+16384
#define SM_KHI       (SM_AB + STAGES * 32768)        // 99328: 2 buffers x (2 x 16KB k-chunks)
#define SM_W         (SM_KHI + 2 * 32768)            // 164864: 2 x 32KB (hi 16KB + lo 16KB)
#define SM_TOTAL     (SM_W + 2 * 32768)              // 230400

// ---------------- TMEM layout (cols) ----------------
#define TM_D1A  0
#define TM_D1B  128
#define TM_D2   256
#define TM_COLS 512

#define SWZ(x) ((x) ^ (((x) >> 3) & 0x70))

// MMA1: kind::f16, dtype=F32(1), atype=btype=BF16(1), N=128, M=128
#define IDESC_MMA1 ((1u<<4) | (1u<<7) | (1u<<10) | ((128u/8u)<<17) | ((128u/16u)<<24))
// MMA2: kind::f16, dtype=F32(1), atype=btype=BF16(1), N=64,  M=128
#define IDESC_MMA2 ((1u<<4) | (1u<<7) | (1u<<10) | ((64u/8u)<<17)  | ((128u/16u)<<24))

// ---------------- scratch ----------------
__device__ float  g_sq[NN];
__device__ float  g_Epart[NSPLIT * NN * SS];              // [split][j][s]
__device__ double g_partial[128];
__device__ int    g_count = 0;
__device__ __align__(1024) char g_Xpk[NTG * NCHUNK * 16384];   // 8 MB bf16 swizzled X chunks
__device__ __align__(1024) char g_Wpk[NTG * 32768];            // 2 MB  swizzled W hi/lo images

// ---------------- helpers ----------------
static __device__ __forceinline__ uint32_t s2u(const void* p) {
    uint32_t a;
    asm("{ .reg .u64 t; cvta.to.shared.u64 t, %1; cvt.u32.u64 %0, t; }" : "=r"(a) : "l"(p));
    return a;
}

#if HAS_TCGEN05 || !defined(__CUDA_ARCH__)

// SW128 K-major SMEM descriptor: layout=2, version=1, SBO=64, LBO=1
static __device__ __forceinline__ uint64_t mkdesc(uint32_t addr) {
    return ((uint64_t)2 << 61) | ((uint64_t)1 << 46) | ((uint64_t)64 << 32) |
           ((uint64_t)1 << 16) | (uint64_t)((addr >> 4) & 0x3FFF);
}

static __device__ __forceinline__ void mbar_init(uint32_t a, uint32_t cnt) {
    asm volatile("mbarrier.init.shared.b64 [%0], %1;" :: "r"(a), "r"(cnt) : "memory");
}
static __device__ __forceinline__ void mbar_arrive(uint32_t a) {
    asm volatile("mbarrier.arrive.shared.b64 _, [%0];" :: "r"(a) : "memory");
}
static __device__ __forceinline__ void mbar_expect_tx(uint32_t a, uint32_t bytes) {
    asm volatile("mbarrier.arrive.expect_tx.shared.b64 _, [%0], %1;"
                 :: "r"(a), "r"(bytes) : "memory");
}
static __device__ __forceinline__ void mbar_wait(uint32_t a, uint32_t parity) {
    asm volatile(
        "{\n\t.reg .pred P;\n\t"
        "WL_%=:\n\t"
        "mbarrier.try_wait.parity.acquire.cta.shared::cta.b64 P, [%0], %1, 0x989680;\n\t"
        "@P bra.uni WD_%=;\n\t"
        "bra.uni WL_%=;\n\t"
        "WD_%=:\n\t}"
        :: "r"(a), "r"(parity) : "memory");
}
static __device__ __forceinline__ void bulk_cp(uint32_t dst, const void* src,
                                               uint32_t bytes, uint32_t mbar) {
    asm volatile(
        "cp.async.bulk.shared::cluster.global.mbarrier::complete_tx::bytes "
        "[%0], [%1], %2, [%3];"
        :: "r"(dst), "l"(src), "r"(bytes), "r"(mbar) : "memory");
}
static __device__ __forceinline__ void tc_commit(uint32_t mbar) {
    asm volatile(
        "tcgen05.commit.cta_group::1.mbarrier::arrive::one.shared::cluster.b64 [%0];"
        :: "r"(mbar) : "memory");
}
static __device__ __forceinline__ void mma_bf16(uint32_t d, uint64_t a, uint64_t b,
                                                uint32_t idesc, uint32_t en) {
    asm volatile(
        "{\n\t.reg .pred p;\n\tsetp.ne.u32 p, %4, 0;\n\t"
        "tcgen05.mma.cta_group::1.kind::f16 [%0], %1, %2, %3, {%5, %5, %5, %5}, p;\n\t}"
        :: "r"(d), "l"(a), "l"(b), "r"(idesc), "r"(en), "r"(0u) : "memory");
}

#define TC_LD_X32(r, addr) \
    asm volatile( \
        "tcgen05.ld.sync.aligned.32x32b.x32.b32 " \
        "{%0, %1, %2, %3, %4, %5, %6, %7, " \
        " %8, %9, %10, %11, %12, %13, %14, %15, " \
        " %16, %17, %18, %19, %20, %21, %22, %23, " \
        " %24, %25, %26, %27, %28, %29, %30, %31}, [%32];" \
        : "=r"((r)[0]),  "=r"((r)[1]),  "=r"((r)[2]),  "=r"((r)[3]), \
          "=r"((r)[4]),  "=r"((r)[5]),  "=r"((r)[6]),  "=r"((r)[7]), \
          "=r"((r)[8]),  "=r"((r)[9]),  "=r"((r)[10]), "=r"((r)[11]), \
          "=r"((r)[12]), "=r"((r)[13]), "=r"((r)[14]), "=r"((r)[15]), \
          "=r"((r)[16]), "=r"((r)[17]), "=r"((r)[18]), "=r"((r)[19]), \
          "=r"((r)[20]), "=r"((r)[21]), "=r"((r)[22]), "=r"((r)[23]), \
          "=r"((r)[24]), "=r"((r)[25]), "=r"((r)[26]), "=r"((r)[27]), \
          "=r"((r)[28]), "=r"((r)[29]), "=r"((r)[30]), "=r"((r)[31]) \
        : "r"(addr))

#define TC_WAIT_LD()      asm volatile("tcgen05.wait::ld.sync.aligned;" ::: "memory")
#define TC_FENCE_AFTER()  asm volatile("tcgen05.fence::after_thread_sync;" ::: "memory")
#define TC_FENCE_BEFORE() asm volatile("tcgen05.fence::before_thread_sync;" ::: "memory")
#define FENCE_ASYNC()     asm volatile("fence.proxy.async.shared::cta;" ::: "memory")

#endif // helpers

// ---------------------------------------------------------------------------
// Kernel 1: row squared norms (exact fp32 X)
// ---------------------------------------------------------------------------
__global__ void rownorm_kernel(const float* __restrict__ X) {
    int row  = blockIdx.x * 8 + (threadIdx.x >> 5);
    int lane = threadIdx.x & 31;
    const float4* xr = reinterpret_cast<const float4*>(X + (size_t)row * DD);
    float s = 0.f;
#pragma unroll
    for (int q = 0; q < 4; q++) {
        float4 v = xr[lane + q * 32];
        s += v.x * v.x + v.y * v.y + v.z * v.z + v.w * v.w;
    }
#pragma unroll
    for (int o = 16; o; o >>= 1) s += __shfl_xor_sync(0xFFFFFFFFu, s, o);
    if (lane == 0) g_sq[row] = s;
}

// ---------------------------------------------------------------------------
// Kernel 1b: pack X into bf16 swizzled 16KB chunk images
// ---------------------------------------------------------------------------
__global__ void xpack_kernel(const float* __restrict__ X) {
    const int gt = blockIdx.x, c = blockIdx.y;
    const int row = threadIdx.x;
    const float* src = &X[(size_t)(gt * TILE + row) * DD + c * 64];
    char* out = g_Xpk + ((size_t)gt * NCHUNK + c) * 16384;
#pragma unroll
    for (int u = 0; u < 8; u++) {
        float4 a = *reinterpret_cast<const float4*>(src + u * 8);
        float4 b = *reinterpret_cast<const float4*>(src + u * 8 + 4);
        __nv_bfloat162 p0 = __floats2bfloat162_rn(a.x, a.y);
        __nv_bfloat162 p1 = __floats2bfloat162_rn(a.z, a.w);
        __nv_bfloat162 p2 = __floats2bfloat162_rn(b.x, b.y);
        __nv_bfloat162 p3 = __floats2bfloat162_rn(b.z, b.w);
        uint4 v;
        v.x = *reinterpret_cast<uint32_t*>(&p0);
        v.y = *reinterpret_cast<uint32_t*>(&p1);
        v.z = *reinterpret_cast<uint32_t*>(&p2);
        v.w = *reinterpret_cast<uint32_t*>(&p3);
        *reinterpret_cast<uint4*>(out + SWZ(row * 128 + u * 16)) = v;
    }
}

// ---------------------------------------------------------------------------
// Kernel 1c: pack W into per-tile bf16 hi/lo swizzled 32KB images
// ---------------------------------------------------------------------------
__global__ void wpack_kernel(const float* __restrict__ W) {
    const int gt = blockIdx.x;
    const int t = threadIdx.x;
    char* out = g_Wpk + (size_t)gt * 32768;
#pragma unroll
    for (int m = 0; m < 32; m++) {
        int flat = m * 256 + t;
        int iw = flat >> 6, s = flat & 63;
        float v = W[(size_t)(gt * TILE + iw) * SS + s];
        __nv_bfloat16 h = __float2bfloat16_rn(v);
        __nv_bfloat16 l = __float2bfloat16_rn(v - __bfloat162float(h));
        int c2 = iw >> 6;
        int sw = SWZ(s * 128 + (iw & 63) * 2);
        *reinterpret_cast<__nv_bfloat16*>(out + c2 * 8192 + sw) = h;
        *reinterpret_cast<__nv_bfloat16*>(out + 16384 + c2 * 8192 + sw) = l;
    }
}

// ---------------------------------------------------------------------------
// Kernel 2: warp-specialized tcgen05 pipeline (R14 protocol, producer split).
// grid (64 j-tiles, 2 i-splits), 192 threads.
//   warp 0 lane 0 : MMA1 issuer (waits ABF/GC, commits ABE/GF)
//   warp 5 lane 0 : copy issuer (waits ABE/EB, expect_tx, bulk copies)
//   warps 1-4     : consumer (R14-identical 4-warp topology)
// Barrier counts/parities identical to R14; only issuing threads differ.
// ---------------------------------------------------------------------------
__global__ __launch_bounds__(192, 1)
void kpca_mma_kernel() {
    extern __shared__ char smem[];
#if HAS_TCGEN05
    const uint32_t sb = s2u(smem);
    const int t    = threadIdx.x;
    const int wid  = t >> 5;
    const int lane = t & 31;
    const int jt     = blockIdx.x;
    const int isplit = blockIdx.y;
    const int j0     = jt * TILE;

    if (wid == 0) {
        asm volatile("tcgen05.alloc.cta_group::1.sync.aligned.shared::cta.b32 [%0], %1;"
                     :: "r"(sb + SM_TMEMPTR), "r"((uint32_t)TM_COLS) : "memory");
    }
    if (t == 0) {
#pragma unroll
        for (int s = 0; s < STAGES; s++) { mbar_init(sb + MB_ABF(s), 1); mbar_init(sb + MB_ABE(s), 1); }
        mbar_init(sb + MB_GF(0), 1);  mbar_init(sb + MB_GF(1), 1);
        mbar_init(sb + MB_GC, 4);
        mbar_init(sb + MB_WF(0), 1);  mbar_init(sb + MB_WF(1), 1);
        mbar_init(sb + MB_EB(0), 1);  mbar_init(sb + MB_EB(1), 1);
    }
    if (t < 128) ((float*)(smem + SM_SQJ))[t] = g_sq[j0 + t] * CEXP;  // premultiplied
    __syncthreads();

    uint32_t tb;
    asm volatile("ld.shared.b32 %0, [%1];" : "=r"(tb) : "r"(sb + SM_TMEMPTR));

    if (wid == 0) {
        // ================= MMA1 ISSUER (warp 0 lane 0) =================
        if (lane == 0) {
            for (int gm = 0; gm < NCH_TOT; gm++) {
                const int it = gm >> 3, c = gm & 7, s = gm % STAGES;
                if (c == 0 && it >= 2) mbar_wait(sb + MB_GC, it & 1);  // epi(it-2) LDTM done
                mbar_wait(sb + MB_ABF(s), (gm / STAGES) & 1);
                uint64_t ad = mkdesc(sb + SM_AB + s * 32768);
                uint64_t bd = mkdesc(sb + SM_AB + s * 32768 + 16384);
                uint32_t d1 = tb + ((it & 1) ? TM_D1B : TM_D1A);
#pragma unroll
                for (int ss = 0; ss < 4; ss++)
                    mma_bf16(d1, ad + ss * 2, bd + ss * 2, IDESC_MMA1, (c | ss) != 0);
                tc_commit(sb + MB_ABE(s));
                if (c == 7) tc_commit(sb + MB_GF(it & 1));
            }
        }
    } else if (wid == 5) {
        // ================= COPY ISSUER (warp 5 lane 0) =================
        if (lane == 0) {
            const char* xpkA = g_Xpk + (size_t)(isplit * NT) * NCHUNK * 16384;
            const char* xpkB = g_Xpk + (size_t)jt * NCHUNK * 16384;
            for (int g = 0; g < NCH_TOT; g++) {
                const int it_c = g >> 3, c_c = g & 7;
                if (c_c == 0) {
                    // W buffer (it_c&1) free once MMA2(it_c-2) done
                    if (it_c >= 2)
                        mbar_wait(sb + MB_EB(it_c & 1), ((it_c >> 1) + 1) & 1);
                    mbar_expect_tx(sb + MB_WF(it_c & 1), 32768);
                    bulk_cp(sb + SM_W + (it_c & 1) * 32768,
                            g_Wpk + (size_t)(isplit * NT + it_c) * 32768,
                            32768, sb + MB_WF(it_c & 1));
                }
                const int s = g % STAGES;
                if (g >= STAGES) mbar_wait(sb + MB_ABE(s), ((g / STAGES) - 1) & 1);
                mbar_expect_tx(sb + MB_ABF(s), 32768);
                bulk_cp(sb + SM_AB + s * 32768,
                        xpkA + ((size_t)it_c * NCHUNK + c_c) * 16384,
                        16384, sb + MB_ABF(s));
                bulk_cp(sb + SM_AB + s * 32768 + 16384,
                        xpkB + (size_t)c_c * 16384,
                        16384, sb + MB_ABF(s));
            }
        }
    } else {
        // ========== CONSUMER (warps 1-4, 128 threads) — R14-identical ==========
        const int sub  = wid & 3;               // TMEM subpartition
        const int iloc = sub * 32 + lane;       // i row owned by this thread
        const int ic   = iloc >> 6;             // k-chunk of MMA2
        const int ii2  = (iloc & 63) * 2;       // byte offset in K row
        const float* sqs = (const float*)(smem + SM_SQJ);   // premultiplied by CEXP

        for (int ite = 0; ite < NT; ite++) {
            const uint32_t d1 = tb + ((ite & 1) ? TM_D1B : TM_D1A);
            const float base = -g_sq[isplit * (NN / NSPLIT) + ite * TILE + iloc] * CEXP;
            const int Kbuf = SM_KHI + (ite & 1) * 32768;   // this tile's K buffer
            const int KhiC = Kbuf + ic * 16384;

            mbar_wait(sb + MB_GF(ite & 1), (ite >> 1) & 1);
            TC_FENCE_AFTER();
            // K buffer (ite&1) free once MMA2(ite-2) done
            if (ite >= 2) mbar_wait(sb + MB_EB(ite & 1), ((ite >> 1) + 1) & 1);

#pragma unroll
            for (int p = 0; p < 2; p++) {
                uint32_t r[64];
                TC_LD_X32(r,      d1 + p * 64);
                TC_LD_X32(r + 32, d1 + p * 64 + 32);
                TC_WAIT_LD();
                if (p == 1 && lane == 0) mbar_arrive(sb + MB_GC);  // D1 WAR release
#pragma unroll
                for (int rr = 0; rr < 64; rr++) {
                    int   j  = p * 64 + rr;
                    float gv = __uint_as_float(r[rr]);
                    // arg = (2*gv - sqi - sqj) * INV2SIG * log2e
                    float v  = exp2f(fmaf(gv, 2.0f * CEXP, base - sqs[j]));
                    *reinterpret_cast<__nv_bfloat16*>(smem + KhiC + SWZ(j * 128 + ii2)) =
                        __float2bfloat16_rn(v);
                }
            }
            FENCE_ASYNC();
            asm volatile("bar.sync 1, 128;" ::: "memory");

            if (t == 32) {   // warp 1 lane 0 issues MMA2 on K buffer (ite&1)
                mbar_wait(sb + MB_WF(ite & 1), (ite >> 1) & 1);
                const uint32_t wb = SM_W + (ite & 1) * 32768;
#pragma unroll
                for (int c2 = 0; c2 < 2; c2++) {
                    uint64_t ah = mkdesc(sb + Kbuf + c2 * 16384);
                    uint64_t bh = mkdesc(sb + wb + c2 * 8192);
                    uint64_t bl = mkdesc(sb + wb + 16384 + c2 * 8192);
#pragma unroll
                    for (int ss = 0; ss < 4; ss++) {
                        uint32_t first = (ite == 0 && c2 == 0 && ss == 0);
                        mma_bf16(tb + TM_D2, ah + ss * 2, bh + ss * 2, IDESC_MMA2, !first);
                        mma_bf16(tb + TM_D2, ah + ss * 2, bl + ss * 2, IDESC_MMA2, 1u);
                    }
                }
                tc_commit(sb + MB_EB(ite & 1));
            }
        }

        // ---------------- final E readout ----------------
        // last MMA2 = tile NT-1 (barrier 1, commit #(NT/2)): parity ((NT>>1)+1)&1
        mbar_wait(sb + MB_EB(1), ((NT >> 1) + 1) & 1);
        TC_FENCE_AFTER();
        {
            uint32_t e[64];
            TC_LD_X32(e,      tb + TM_D2);
            TC_LD_X32(e + 32, tb + TM_D2 + 32);
            TC_WAIT_LD();
            TC_FENCE_BEFORE();
            float* dst = &g_Epart[(size_t)isplit * NN * SS + (size_t)(j0 + iloc) * SS];
#pragma unroll
            for (int q = 0; q < 16; q++)
                reinterpret_cast<float4*>(dst)[q] =
                    make_float4(__uint_as_float(e[q * 4 + 0]), __uint_as_float(e[q * 4 + 1]),
                                __uint_as_float(e[q * 4 + 2]), __uint_as_float(e[q * 4 + 3]));
        }
    }

    __syncthreads();
    if (wid == 0) {
        asm volatile("tcgen05.relinquish_alloc_permit.cta_group::1.sync.aligned;" ::: "memory");
        asm volatile("tcgen05.dealloc.cta_group::1.sync.aligned.b32 %0, %1;"
                     :: "r"(tb), "r"((uint32_t)TM_COLS));
    }
#else
    (void)smem;
#endif
}

// ---------------------------------------------------------------------------
// Kernel 3: combine E partials -> loss contributions -> block reduce ->
// last block does the final reduction + nonlinearity (fused, deterministic).
// grid 128 x 1024; each thread handles 4 elements.
// ---------------------------------------------------------------------------
__global__ void finalize_kernel(const float* __restrict__ W,
                                const float* __restrict__ invl,
                                float* __restrict__ out) {
    const int tid = threadIdx.x;
    const int b   = blockIdx.x;

    double contrib = 0.0;
#pragma unroll
    for (int q = 0; q < 4; q++) {
        int idx = b * 4096 + q * 1024 + tid;
        int j = idx >> 6;
        int s = idx & 63;
        float E = g_Epart[idx] + g_Epart[NN * SS + idx];
        double Ed = (double)E;
        contrib += 0.5 * Ed * ((double)W[(size_t)j * SS + s] - (double)invl[s] * Ed);
    }

    __shared__ double sm[1024];
    sm[tid] = contrib;
    __syncthreads();
#pragma unroll
    for (int o = 512; o; o >>= 1) {
        if (tid < o) sm[tid] += sm[tid + o];
        __syncthreads();
    }

    __shared__ int isLast;
    if (tid == 0) {
        g_partial[b] = sm[0];
        __threadfence();
        isLast = (atomicAdd(&g_count, 1) == 127);
    }
    __syncthreads();

    if (isLast) {
        // deterministic: fixed-order tree over the 128 partials
        double v = (tid < 128) ? g_partial[tid] : 0.0;
        sm[tid] = v;
        __syncthreads();
#pragma unroll
        for (int o = 64; o; o >>= 1) {
            if (tid < o) sm[tid] += sm[tid + o];
            __syncthreads();
        }
        if (tid == 0) {
            double L = sm[0];
            out[0] = (float)(L + 0.05 * L * L);
            g_count = 0;   // reset for next graph replay
        }
    }
}

// ---------------------------------------------------------------------------
extern "C" void kernel_launch(void* const* d_in, const int* in_sizes, int n_in,
                              void* d_out, int out_size) {
    const float* X    = (const float*)d_in[0];   // [8192, 512]
    const float* W    = (const float*)d_in[1];   // [8192, 64]
    const float* invl = (const float*)d_in[2];   // [64]
    float* out = (float*)d_out;

    cudaFuncSetAttribute(kpca_mma_kernel,
                         cudaFuncAttributeMaxDynamicSharedMemorySize, SM_TOTAL);

    rownorm_kernel<<<NN / 8, 256>>>(X);
    xpack_kernel<<<dim3(NTG, NCHUNK), 128>>>(X);
    wpack_kernel<<<NTG, 256>>>(W);
    kpca_mma_kernel<<<dim3(NTG, NSPLIT), 192, SM_TOTAL>>>();
    finalize_kernel<<<128, 1024>>>(W, invl, out);
}